// round 1
// baseline (speedup 1.0000x reference)
#include <cuda_runtime.h>
#include <cstdint>

#define MAXN 100000

// ---------------- scratch (device globals; no allocation allowed) ----------
__device__ __align__(16) float g_Wc[128 * 256];        // packed [k][c] weights
__device__ __align__(16) float g_self[MAXN * 128];     // relu(vecs@W0+b0) -> normalized in place
__device__ __align__(16) float g_vw[MAXN * 128];       // vecs@W1 (col j = h*32+k)
__device__ __align__(16) float g_agg[MAXN * 128];      // edge-aggregated messages
__device__ __align__(16) float g_a0[MAXN * 4];         // a_self[n][h]
__device__ __align__(16) float g_a1[MAXN * 4];         // a_neigh[n][h]

// ---------------- f32x2 packed-FMA helpers ---------------------------------
__device__ __forceinline__ unsigned long long pk2(float lo, float hi) {
    unsigned long long r;
    asm("mov.b64 %0, {%1, %2};" : "=l"(r) : "f"(lo), "f"(hi));
    return r;
}
__device__ __forceinline__ void up2(unsigned long long v, float& lo, float& hi) {
    asm("mov.b64 {%0, %1}, %2;" : "=f"(lo), "=f"(hi) : "l"(v));
}
__device__ __forceinline__ void fma2(unsigned long long& acc, unsigned long long a,
                                     unsigned long long b) {
    asm("fma.rn.f32x2 %0, %1, %2, %0;" : "+l"(acc) : "l"(a), "l"(b));
}

// ---------------- kernel 0: pack weights [k][c], c<128 -> W0, c>=128 -> W1 --
__global__ void pack_kernel(const float* __restrict__ W0, const float* __restrict__ W1) {
    int idx = blockIdx.x * blockDim.x + threadIdx.x;   // < 32768
    int k = idx >> 8;
    int c = idx & 255;
    float v;
    if (c < 128) {
        v = W0[k * 128 + c];
    } else {
        int j = c - 128;
        int h = j >> 5;
        int kk = j & 31;
        v = W1[(h * 128 + k) * 32 + kk];
    }
    g_Wc[idx] = v;
}

// ---------------- kernel 1: fused GEMM [N,128] x [128,256] ------------------
// CTA: 256 threads, 64 rows x 256 cols. Thread (rt=tid/32, ct=tid%32):
// rows rt*8..rt*8+7 (as 4 row-pairs), cols ct + c*32, c=0..7.
__global__ __launch_bounds__(256) void gemm_kernel(const float* __restrict__ vecs,
                                                   const float* __restrict__ b0, int n) {
    __shared__ float2 As2[128 * 33];   // [k][row-pair], row stride 66 floats (pad)
    float* Asf = reinterpret_cast<float*>(As2);
    int tid = threadIdx.x;
    int row0 = blockIdx.x * 64;

    // load A tile (64 rows x 128 k), As layout [k][row]
#pragma unroll
    for (int i = 0; i < 32; i++) {
        int idx = tid + i * 256;            // 0..8191
        int r = idx >> 7;
        int k = idx & 127;
        float v = 0.f;
        int gr = row0 + r;
        if (gr < n) v = vecs[(size_t)gr * 128 + k];
        Asf[k * 66 + r] = v;
    }
    __syncthreads();

    int ct = tid & 31;
    int rt = tid >> 5;

    unsigned long long acc[4][8];
#pragma unroll
    for (int r2 = 0; r2 < 4; r2++)
#pragma unroll
        for (int c = 0; c < 8; c++) acc[r2][c] = 0ull;

    const float* Bb = g_Wc + ct;

#pragma unroll 4
    for (int k = 0; k < 128; k++) {
        unsigned long long a[4];
#pragma unroll
        for (int r2 = 0; r2 < 4; r2++)
            a[r2] = *reinterpret_cast<const unsigned long long*>(&As2[k * 33 + rt * 4 + r2]);
#pragma unroll
        for (int c = 0; c < 8; c++) {
            float b = __ldg(&Bb[k * 256 + c * 32]);
            unsigned long long b2 = pk2(b, b);
#pragma unroll
            for (int r2 = 0; r2 < 4; r2++) fma2(acc[r2][c], a[r2], b2);
        }
    }

    // epilogue: c<4 -> self (bias+relu), c>=4 -> vw (raw)
#pragma unroll
    for (int r2 = 0; r2 < 4; r2++) {
        int ga = row0 + rt * 8 + 2 * r2;
#pragma unroll
        for (int c = 0; c < 8; c++) {
            float lo, hi;
            up2(acc[r2][c], lo, hi);
            int j = ct + c * 32;
            if (c < 4) {
                float bb = b0[j];
                if (ga < n)     g_self[(size_t)ga * 128 + j]       = fmaxf(lo + bb, 0.f);
                if (ga + 1 < n) g_self[(size_t)(ga + 1) * 128 + j] = fmaxf(hi + bb, 0.f);
            } else {
                int j2 = j - 128;
                if (ga < n)     g_vw[(size_t)ga * 128 + j2]        = lo;
                if (ga + 1 < n) g_vw[(size_t)(ga + 1) * 128 + j2]  = hi;
            }
        }
    }
}

// ---------------- kernel 2: row-norm of self, attention dots, zero agg -----
__global__ __launch_bounds__(256) void rowpost_kernel(
    const float* __restrict__ att0, const float* __restrict__ att1,
    const float* __restrict__ attb0, const float* __restrict__ attb1,
    const float* __restrict__ off0, const float* __restrict__ sc0, int n) {
    int r = (blockIdx.x << 3) + (threadIdx.x >> 5);
    if (r >= n) return;
    int lane = threadIdx.x & 31;
    int j = lane << 2;

    // self path row-norm
    float4 s = *reinterpret_cast<const float4*>(&g_self[(size_t)r * 128 + j]);
    float sum = s.x + s.y + s.z + s.w;
    float sq = s.x * s.x + s.y * s.y + s.z * s.z + s.w * s.w;
#pragma unroll
    for (int m = 16; m > 0; m >>= 1) {
        sum += __shfl_xor_sync(0xffffffffu, sum, m);
        sq  += __shfl_xor_sync(0xffffffffu, sq, m);
    }
    float mean = sum * (1.f / 128.f);
    float var = fmaxf(sq * (1.f / 128.f) - mean * mean, 0.f);
    float rs = rsqrtf(var + 1e-9f);
    float4 o;
    o.x = sc0[j + 0] * (s.x - mean) * rs + off0[j + 0];
    o.y = sc0[j + 1] * (s.y - mean) * rs + off0[j + 1];
    o.z = sc0[j + 2] * (s.z - mean) * rs + off0[j + 2];
    o.w = sc0[j + 3] * (s.w - mean) * rs + off0[j + 3];
    *reinterpret_cast<float4*>(&g_self[(size_t)r * 128 + j]) = o;

    // attention logits per head (segmented 8-lane reduce)
    float4 v  = *reinterpret_cast<const float4*>(&g_vw[(size_t)r * 128 + j]);
    float4 w0 = *reinterpret_cast<const float4*>(&att0[j]);
    float4 w1 = *reinterpret_cast<const float4*>(&att1[j]);
    float d0 = v.x * w0.x + v.y * w0.y + v.z * w0.z + v.w * w0.w;
    float d1 = v.x * w1.x + v.y * w1.y + v.z * w1.z + v.w * w1.w;
#pragma unroll
    for (int m = 1; m < 8; m <<= 1) {
        d0 += __shfl_xor_sync(0xffffffffu, d0, m);
        d1 += __shfl_xor_sync(0xffffffffu, d1, m);
    }
    if ((lane & 7) == 0) {
        int h = lane >> 3;
        g_a0[(size_t)r * 4 + h] = d0 + attb0[h];
        g_a1[(size_t)r * 4 + h] = d1 + attb1[h];
    }

    // zero agg
    float4 z = make_float4(0.f, 0.f, 0.f, 0.f);
    *reinterpret_cast<float4*>(&g_agg[(size_t)r * 128 + j]) = z;
}

// ---------------- kernel 3: edge scatter (warp per edge) -------------------
__global__ __launch_bounds__(256) void edge_kernel(const float* __restrict__ vals,
                                                   const int* __restrict__ rows,
                                                   const int* __restrict__ cols, int e) {
    int w32 = (blockIdx.x << 3) + (threadIdx.x >> 5);
    if (w32 >= e) return;
    int lane = threadIdx.x & 31;
    int r = __ldg(rows + w32);
    int c = __ldg(cols + w32);
    float val = __ldg(vals + w32);
    int h = lane >> 3;
    float a0 = __ldg(&g_a0[(size_t)r * 4 + h]);   // a_self at dest row
    float a1 = __ldg(&g_a1[(size_t)c * 4 + h]);   // a_neigh at source col
    float w = val * fmaxf(a0 + a1, 0.f);
    if (w != 0.f) {
        float4 v = *reinterpret_cast<const float4*>(&g_vw[(size_t)c * 128 + (lane << 2)]);
        float* dst = &g_agg[(size_t)r * 128 + (lane << 2)];
        asm volatile("red.global.add.v4.f32 [%0], {%1, %2, %3, %4};"
                     :: "l"(dst), "f"(v.x * w), "f"(v.y * w), "f"(v.z * w), "f"(v.w * w)
                     : "memory");
    }
}

// ---------------- kernel 4: relu+bias, row-norm, add self, write out -------
__global__ __launch_bounds__(256) void final_kernel(const float* __restrict__ b1,
                                                    const float* __restrict__ off1,
                                                    const float* __restrict__ sc1,
                                                    float* __restrict__ out, int n) {
    int r = (blockIdx.x << 3) + (threadIdx.x >> 5);
    if (r >= n) return;
    int lane = threadIdx.x & 31;
    int j = lane << 2;
    float4 a = *reinterpret_cast<const float4*>(&g_agg[(size_t)r * 128 + j]);
    float t0 = fmaxf(a.x, 0.f) + b1[j + 0];
    float t1 = fmaxf(a.y, 0.f) + b1[j + 1];
    float t2 = fmaxf(a.z, 0.f) + b1[j + 2];
    float t3 = fmaxf(a.w, 0.f) + b1[j + 3];
    float sum = t0 + t1 + t2 + t3;
    float sq = t0 * t0 + t1 * t1 + t2 * t2 + t3 * t3;
#pragma unroll
    for (int m = 16; m > 0; m >>= 1) {
        sum += __shfl_xor_sync(0xffffffffu, sum, m);
        sq  += __shfl_xor_sync(0xffffffffu, sq, m);
    }
    float mean = sum * (1.f / 128.f);
    float var = fmaxf(sq * (1.f / 128.f) - mean * mean, 0.f);
    float rs = rsqrtf(var + 1e-9f);
    float4 s = *reinterpret_cast<const float4*>(&g_self[(size_t)r * 128 + j]);
    float4 o;
    o.x = sc1[j + 0] * (t0 - mean) * rs + off1[j + 0] + s.x;
    o.y = sc1[j + 1] * (t1 - mean) * rs + off1[j + 1] + s.y;
    o.z = sc1[j + 2] * (t2 - mean) * rs + off1[j + 2] + s.z;
    o.w = sc1[j + 3] * (t3 - mean) * rs + off1[j + 3] + s.w;
    *reinterpret_cast<float4*>(&out[(size_t)r * 128 + j]) = o;
}

// ---------------- launch ----------------------------------------------------
extern "C" void kernel_launch(void* const* d_in, const int* in_sizes, int n_in,
                              void* d_out, int out_size) {
    const float* vecs     = (const float*)d_in[0];
    const float* adj_vals = (const float*)d_in[1];
    const float* W0       = (const float*)d_in[2];
    const float* b0       = (const float*)d_in[3];
    const float* W1       = (const float*)d_in[4];
    const float* b1       = (const float*)d_in[5];
    const float* att0     = (const float*)d_in[6];
    const float* att1     = (const float*)d_in[7];
    const float* attb0    = (const float*)d_in[8];
    const float* attb1    = (const float*)d_in[9];
    const float* off0     = (const float*)d_in[10];
    const float* sc0      = (const float*)d_in[11];
    const float* off1     = (const float*)d_in[12];
    const float* sc1      = (const float*)d_in[13];
    const int*   rows     = (const int*)d_in[14];
    const int*   cols     = (const int*)d_in[15];

    int n = in_sizes[0] / 128;
    int e = in_sizes[1];
    float* out = (float*)d_out;

    pack_kernel<<<128, 256>>>(W0, W1);
    gemm_kernel<<<(n + 63) / 64, 256>>>(vecs, b0, n);
    rowpost_kernel<<<(n + 7) / 8, 256>>>(att0, att1, attb0, attb1, off0, sc0, n);
    edge_kernel<<<(e + 7) / 8, 256>>>(adj_vals, rows, cols, e);
    final_kernel<<<(n + 7) / 8, 256>>>(b1, off1, sc1, out, n);
}

// round 2
// speedup vs baseline: 1.2655x; 1.2655x over previous
#include <cuda_runtime.h>
#include <cstdint>

#define MAXN 100000
#define MAXE 1600000

// ---------------- scratch (device globals; no allocation allowed) ----------
__device__ __align__(16) float g_Wc[128 * 256];        // packed [k][c] weights
__device__ __align__(16) float g_self[MAXN * 128];     // relu(vecs@W0+b0) -> normalized in place
__device__ __align__(16) float g_vw[MAXN * 128];       // vecs@W1 (col j = h*32+k)
__device__ __align__(16) float g_a0[MAXN * 4];         // a_self[n][h]
__device__ __align__(16) float g_a1[MAXN * 4];         // a_neigh[n][h]
__device__ int   g_cnt[MAXN];                          // passing-edge count per dest row
__device__ int   g_start[MAXN];                        // exclusive scan of counts
__device__ int   g_cursor[MAXN];                       // scatter cursors
__device__ int   g_bsum[512];
__device__ int   g_boff[512];
__device__ unsigned int g_ecol[MAXE];                  // compacted source col per record
__device__ __align__(16) float4 g_ew4[MAXE];           // per-head weights per record

// ---------------- f32x2 packed-FMA helpers ---------------------------------
__device__ __forceinline__ unsigned long long pk2(float lo, float hi) {
    unsigned long long r;
    asm("mov.b64 %0, {%1, %2};" : "=l"(r) : "f"(lo), "f"(hi));
    return r;
}
__device__ __forceinline__ void up2(unsigned long long v, float& lo, float& hi) {
    asm("mov.b64 {%0, %1}, %2;" : "=f"(lo), "=f"(hi) : "l"(v));
}
__device__ __forceinline__ void fma2(unsigned long long& acc, unsigned long long a,
                                     unsigned long long b) {
    asm("fma.rn.f32x2 %0, %1, %2, %0;" : "+l"(acc) : "l"(a), "l"(b));
}

// ---------------- kernel 0: pack weights [k][c], c<128 -> W0, c>=128 -> W1 --
__global__ void pack_kernel(const float* __restrict__ W0, const float* __restrict__ W1) {
    int idx = blockIdx.x * blockDim.x + threadIdx.x;   // < 32768
    int k = idx >> 8;
    int c = idx & 255;
    float v;
    if (c < 128) {
        v = W0[k * 128 + c];
    } else {
        int j = c - 128;
        int h = j >> 5;
        int kk = j & 31;
        v = W1[(h * 128 + k) * 32 + kk];
    }
    g_Wc[idx] = v;
}

// ---------------- kernel 1: fused GEMM [N,128] x [128,256] ------------------
__global__ __launch_bounds__(256) void gemm_kernel(const float* __restrict__ vecs,
                                                   const float* __restrict__ b0, int n) {
    __shared__ float2 As2[128 * 33];   // [k][row-pair], row stride 66 floats (pad)
    float* Asf = reinterpret_cast<float*>(As2);
    int tid = threadIdx.x;
    int row0 = blockIdx.x * 64;

#pragma unroll
    for (int i = 0; i < 32; i++) {
        int idx = tid + i * 256;            // 0..8191
        int r = idx >> 7;
        int k = idx & 127;
        float v = 0.f;
        int gr = row0 + r;
        if (gr < n) v = vecs[(size_t)gr * 128 + k];
        Asf[k * 66 + r] = v;
    }
    __syncthreads();

    int ct = tid & 31;
    int rt = tid >> 5;

    unsigned long long acc[4][8];
#pragma unroll
    for (int r2 = 0; r2 < 4; r2++)
#pragma unroll
        for (int c = 0; c < 8; c++) acc[r2][c] = 0ull;

    const float* Bb = g_Wc + ct;

#pragma unroll 4
    for (int k = 0; k < 128; k++) {
        unsigned long long a[4];
#pragma unroll
        for (int r2 = 0; r2 < 4; r2++)
            a[r2] = *reinterpret_cast<const unsigned long long*>(&As2[k * 33 + rt * 4 + r2]);
#pragma unroll
        for (int c = 0; c < 8; c++) {
            float b = __ldg(&Bb[k * 256 + c * 32]);
            unsigned long long b2 = pk2(b, b);
#pragma unroll
            for (int r2 = 0; r2 < 4; r2++) fma2(acc[r2][c], a[r2], b2);
        }
    }

#pragma unroll
    for (int r2 = 0; r2 < 4; r2++) {
        int ga = row0 + rt * 8 + 2 * r2;
#pragma unroll
        for (int c = 0; c < 8; c++) {
            float lo, hi;
            up2(acc[r2][c], lo, hi);
            int j = ct + c * 32;
            if (c < 4) {
                float bb = b0[j];
                if (ga < n)     g_self[(size_t)ga * 128 + j]       = fmaxf(lo + bb, 0.f);
                if (ga + 1 < n) g_self[(size_t)(ga + 1) * 128 + j] = fmaxf(hi + bb, 0.f);
            } else {
                int j2 = j - 128;
                if (ga < n)     g_vw[(size_t)ga * 128 + j2]        = lo;
                if (ga + 1 < n) g_vw[(size_t)(ga + 1) * 128 + j2]  = hi;
            }
        }
    }
}

// ---------------- kernel 2: row-norm of self, attention dots, zero counts --
__global__ __launch_bounds__(256) void rowpost_kernel(
    const float* __restrict__ att0, const float* __restrict__ att1,
    const float* __restrict__ attb0, const float* __restrict__ attb1,
    const float* __restrict__ off0, const float* __restrict__ sc0, int n) {
    int r = (blockIdx.x << 3) + (threadIdx.x >> 5);
    if (r >= n) return;
    int lane = threadIdx.x & 31;
    int j = lane << 2;

    float4 s = *reinterpret_cast<const float4*>(&g_self[(size_t)r * 128 + j]);
    float sum = s.x + s.y + s.z + s.w;
    float sq = s.x * s.x + s.y * s.y + s.z * s.z + s.w * s.w;
#pragma unroll
    for (int m = 16; m > 0; m >>= 1) {
        sum += __shfl_xor_sync(0xffffffffu, sum, m);
        sq  += __shfl_xor_sync(0xffffffffu, sq, m);
    }
    float mean = sum * (1.f / 128.f);
    float var = fmaxf(sq * (1.f / 128.f) - mean * mean, 0.f);
    float rs = rsqrtf(var + 1e-9f);
    float4 o;
    o.x = sc0[j + 0] * (s.x - mean) * rs + off0[j + 0];
    o.y = sc0[j + 1] * (s.y - mean) * rs + off0[j + 1];
    o.z = sc0[j + 2] * (s.z - mean) * rs + off0[j + 2];
    o.w = sc0[j + 3] * (s.w - mean) * rs + off0[j + 3];
    *reinterpret_cast<float4*>(&g_self[(size_t)r * 128 + j]) = o;

    float4 v  = *reinterpret_cast<const float4*>(&g_vw[(size_t)r * 128 + j]);
    float4 w0 = *reinterpret_cast<const float4*>(&att0[j]);
    float4 w1 = *reinterpret_cast<const float4*>(&att1[j]);
    float d0 = v.x * w0.x + v.y * w0.y + v.z * w0.z + v.w * w0.w;
    float d1 = v.x * w1.x + v.y * w1.y + v.z * w1.z + v.w * w1.w;
#pragma unroll
    for (int m = 1; m < 8; m <<= 1) {
        d0 += __shfl_xor_sync(0xffffffffu, d0, m);
        d1 += __shfl_xor_sync(0xffffffffu, d1, m);
    }
    if ((lane & 7) == 0) {
        int h = lane >> 3;
        g_a0[(size_t)r * 4 + h] = d0 + attb0[h];
        g_a1[(size_t)r * 4 + h] = d1 + attb1[h];
    }
    if (lane == 0) g_cnt[r] = 0;
}

// ---------------- kernel 3: histogram of passing edges per dest row --------
__global__ __launch_bounds__(256) void hist_kernel(const float* __restrict__ vals,
                                                   const int* __restrict__ rows,
                                                   const int* __restrict__ cols, int e) {
    int i = blockIdx.x * 256 + threadIdx.x;
    if (i >= e) return;
    int r = __ldg(rows + i);
    int c = __ldg(cols + i);
    float val = __ldg(vals + i);
    float4 ar = __ldg(reinterpret_cast<const float4*>(&g_a0[(size_t)r * 4]));
    float4 ac = __ldg(reinterpret_cast<const float4*>(&g_a1[(size_t)c * 4]));
    float w0 = val * fmaxf(ar.x + ac.x, 0.f);
    float w1 = val * fmaxf(ar.y + ac.y, 0.f);
    float w2 = val * fmaxf(ar.z + ac.z, 0.f);
    float w3 = val * fmaxf(ar.w + ac.w, 0.f);
    if (w0 + w1 + w2 + w3 > 0.f) atomicAdd(&g_cnt[r], 1);
}

// ---------------- scan kernels ----------------------------------------------
__global__ __launch_bounds__(256) void scanA_kernel(int n) {
    int t = threadIdx.x;
    int i = blockIdx.x * 256 + t;
    int v = (i < n) ? g_cnt[i] : 0;
#pragma unroll
    for (int m = 16; m > 0; m >>= 1) v += __shfl_xor_sync(0xffffffffu, v, m);
    __shared__ int ws[8];
    if ((t & 31) == 0) ws[t >> 5] = v;
    __syncthreads();
    if (t == 0) {
        int s = 0;
#pragma unroll
        for (int k = 0; k < 8; k++) s += ws[k];
        g_bsum[blockIdx.x] = s;
    }
}

__global__ __launch_bounds__(512) void scanB_kernel(int nb) {
    __shared__ int s[512];
    int t = threadIdx.x;
    int v = (t < nb) ? g_bsum[t] : 0;
    s[t] = v;
    __syncthreads();
#pragma unroll
    for (int off = 1; off < 512; off <<= 1) {
        int x = (t >= off) ? s[t - off] : 0;
        __syncthreads();
        s[t] += x;
        __syncthreads();
    }
    g_boff[t] = s[t] - v;   // exclusive
}

__global__ __launch_bounds__(256) void scanC_kernel(int n) {
    __shared__ int s[256];
    int t = threadIdx.x;
    int i = blockIdx.x * 256 + t;
    int v = (i < n) ? g_cnt[i] : 0;
    s[t] = v;
    __syncthreads();
#pragma unroll
    for (int off = 1; off < 256; off <<= 1) {
        int x = (t >= off) ? s[t - off] : 0;
        __syncthreads();
        s[t] += x;
        __syncthreads();
    }
    if (i < n) {
        int start = s[t] - v + g_boff[blockIdx.x];
        g_start[i] = start;
        g_cursor[i] = start;
    }
}

// ---------------- kernel 4: scatter compacted edge records ------------------
__global__ __launch_bounds__(256) void scatter_kernel(const float* __restrict__ vals,
                                                      const int* __restrict__ rows,
                                                      const int* __restrict__ cols, int e) {
    int i = blockIdx.x * 256 + threadIdx.x;
    if (i >= e) return;
    int r = __ldg(rows + i);
    int c = __ldg(cols + i);
    float val = __ldg(vals + i);
    float4 ar = __ldg(reinterpret_cast<const float4*>(&g_a0[(size_t)r * 4]));
    float4 ac = __ldg(reinterpret_cast<const float4*>(&g_a1[(size_t)c * 4]));
    float4 w;
    w.x = val * fmaxf(ar.x + ac.x, 0.f);
    w.y = val * fmaxf(ar.y + ac.y, 0.f);
    w.z = val * fmaxf(ar.z + ac.z, 0.f);
    w.w = val * fmaxf(ar.w + ac.w, 0.f);
    if (w.x + w.y + w.z + w.w > 0.f) {
        int pos = atomicAdd(&g_cursor[r], 1);
        g_ecol[pos] = (unsigned int)c;
        g_ew4[pos] = w;
    }
}

// ---------------- kernel 5: per-row aggregation + fused epilogue ------------
__global__ __launch_bounds__(256) void agg_kernel(const float* __restrict__ b1,
                                                  const float* __restrict__ off1,
                                                  const float* __restrict__ sc1,
                                                  float* __restrict__ out, int n) {
    int r = (blockIdx.x << 3) + (threadIdx.x >> 5);
    if (r >= n) return;
    int lane = threadIdx.x & 31;
    int j = lane << 2;
    int h = lane >> 3;

    int start = g_start[r];
    int deg = g_cnt[r];

    float4 acc = make_float4(0.f, 0.f, 0.f, 0.f);
    const float* wbase = reinterpret_cast<const float*>(g_ew4);

    int i = 0;
    for (; i + 4 <= deg; i += 4) {
        unsigned int c0 = __ldg(&g_ecol[start + i + 0]);
        unsigned int c1 = __ldg(&g_ecol[start + i + 1]);
        unsigned int c2 = __ldg(&g_ecol[start + i + 2]);
        unsigned int c3 = __ldg(&g_ecol[start + i + 3]);
        float w0 = __ldg(wbase + (size_t)(start + i + 0) * 4 + h);
        float w1 = __ldg(wbase + (size_t)(start + i + 1) * 4 + h);
        float w2 = __ldg(wbase + (size_t)(start + i + 2) * 4 + h);
        float w3 = __ldg(wbase + (size_t)(start + i + 3) * 4 + h);
        float4 v0, v1, v2, v3;
        if (w0 > 0.f) {
            v0 = __ldg(reinterpret_cast<const float4*>(&g_vw[(size_t)c0 * 128 + j]));
            acc.x += w0 * v0.x; acc.y += w0 * v0.y; acc.z += w0 * v0.z; acc.w += w0 * v0.w;
        }
        if (w1 > 0.f) {
            v1 = __ldg(reinterpret_cast<const float4*>(&g_vw[(size_t)c1 * 128 + j]));
            acc.x += w1 * v1.x; acc.y += w1 * v1.y; acc.z += w1 * v1.z; acc.w += w1 * v1.w;
        }
        if (w2 > 0.f) {
            v2 = __ldg(reinterpret_cast<const float4*>(&g_vw[(size_t)c2 * 128 + j]));
            acc.x += w2 * v2.x; acc.y += w2 * v2.y; acc.z += w2 * v2.z; acc.w += w2 * v2.w;
        }
        if (w3 > 0.f) {
            v3 = __ldg(reinterpret_cast<const float4*>(&g_vw[(size_t)c3 * 128 + j]));
            acc.x += w3 * v3.x; acc.y += w3 * v3.y; acc.z += w3 * v3.z; acc.w += w3 * v3.w;
        }
    }
    for (; i < deg; i++) {
        unsigned int c = __ldg(&g_ecol[start + i]);
        float w = __ldg(wbase + (size_t)(start + i) * 4 + h);
        if (w > 0.f) {
            float4 v = __ldg(reinterpret_cast<const float4*>(&g_vw[(size_t)c * 128 + j]));
            acc.x += w * v.x; acc.y += w * v.y; acc.z += w * v.z; acc.w += w * v.w;
        }
    }

    // fused final epilogue: relu + bias, row-norm, add normalized self, write
    float t0 = fmaxf(acc.x, 0.f) + b1[j + 0];
    float t1 = fmaxf(acc.y, 0.f) + b1[j + 1];
    float t2 = fmaxf(acc.z, 0.f) + b1[j + 2];
    float t3 = fmaxf(acc.w, 0.f) + b1[j + 3];
    float sum = t0 + t1 + t2 + t3;
    float sq = t0 * t0 + t1 * t1 + t2 * t2 + t3 * t3;
#pragma unroll
    for (int m = 16; m > 0; m >>= 1) {
        sum += __shfl_xor_sync(0xffffffffu, sum, m);
        sq  += __shfl_xor_sync(0xffffffffu, sq, m);
    }
    float mean = sum * (1.f / 128.f);
    float var = fmaxf(sq * (1.f / 128.f) - mean * mean, 0.f);
    float rs = rsqrtf(var + 1e-9f);
    float4 s = *reinterpret_cast<const float4*>(&g_self[(size_t)r * 128 + j]);
    float4 o;
    o.x = sc1[j + 0] * (t0 - mean) * rs + off1[j + 0] + s.x;
    o.y = sc1[j + 1] * (t1 - mean) * rs + off1[j + 1] + s.y;
    o.z = sc1[j + 2] * (t2 - mean) * rs + off1[j + 2] + s.z;
    o.w = sc1[j + 3] * (t3 - mean) * rs + off1[j + 3] + s.w;
    *reinterpret_cast<float4*>(&out[(size_t)r * 128 + j]) = o;
}

// ---------------- launch ----------------------------------------------------
extern "C" void kernel_launch(void* const* d_in, const int* in_sizes, int n_in,
                              void* d_out, int out_size) {
    const float* vecs     = (const float*)d_in[0];
    const float* adj_vals = (const float*)d_in[1];
    const float* W0       = (const float*)d_in[2];
    const float* b0       = (const float*)d_in[3];
    const float* W1       = (const float*)d_in[4];
    const float* b1       = (const float*)d_in[5];
    const float* att0     = (const float*)d_in[6];
    const float* att1     = (const float*)d_in[7];
    const float* attb0    = (const float*)d_in[8];
    const float* attb1    = (const float*)d_in[9];
    const float* off0     = (const float*)d_in[10];
    const float* sc0      = (const float*)d_in[11];
    const float* off1     = (const float*)d_in[12];
    const float* sc1      = (const float*)d_in[13];
    const int*   rows     = (const int*)d_in[14];
    const int*   cols     = (const int*)d_in[15];

    int n = in_sizes[0] / 128;
    int e = in_sizes[1];
    float* out = (float*)d_out;

    int nb = (n + 255) / 256;

    pack_kernel<<<128, 256>>>(W0, W1);
    gemm_kernel<<<(n + 63) / 64, 256>>>(vecs, b0, n);
    rowpost_kernel<<<(n + 7) / 8, 256>>>(att0, att1, attb0, attb1, off0, sc0, n);
    hist_kernel<<<(e + 255) / 256, 256>>>(adj_vals, rows, cols, e);
    scanA_kernel<<<nb, 256>>>(n);
    scanB_kernel<<<1, 512>>>(nb);
    scanC_kernel<<<nb, 256>>>(n);
    scatter_kernel<<<(e + 255) / 256, 256>>>(adj_vals, rows, cols, e);
    agg_kernel<<<(n + 7) / 8, 256>>>(b1, off1, sc1, out, n);
}

// round 4
// speedup vs baseline: 1.6595x; 1.3114x over previous
#include <cuda_runtime.h>
#include <cuda_bf16.h>
#include <cstdint>

#define MAXN 100000
#define MAXE 1600000

// ---------------- scratch (device globals; no allocation allowed) ----------
// B packed: [half(2)][split(2)][kchunk(8)][n(128)][16 bf16] = 131072 bytes
__device__ __align__(16) uint8_t g_Bpk[131072];
__device__ __align__(16) float g_self[MAXN * 128];
__device__ __align__(16) float g_vw[MAXN * 128];
__device__ __align__(16) float g_a0[MAXN * 4];
__device__ __align__(16) float g_a1[MAXN * 4];
__device__ int   g_cnt[MAXN];
__device__ int   g_start[MAXN];
__device__ int   g_cursor[MAXN];
__device__ int   g_bsum[512];
__device__ int   g_boff[512];
__device__ unsigned int g_ecol[MAXE];
__device__ __align__(16) float4 g_ew4[MAXE];

// ---------------- helpers ---------------------------------------------------
__device__ __forceinline__ uint32_t smem_u32(const void* p) {
    uint32_t a;
    asm("{ .reg .u64 t; cvta.to.shared.u64 t, %1; cvt.u32.u64 %0, t; }" : "=r"(a) : "l"(p));
    return a;
}
__device__ __forceinline__ void ldsm4(uint32_t addr, uint32_t& r0, uint32_t& r1,
                                      uint32_t& r2, uint32_t& r3) {
    asm volatile("ldmatrix.sync.aligned.m8n8.x4.shared.b16 {%0,%1,%2,%3}, [%4];"
                 : "=r"(r0), "=r"(r1), "=r"(r2), "=r"(r3) : "r"(addr));
}
__device__ __forceinline__ void mma16816(float* c, uint32_t a0, uint32_t a1, uint32_t a2,
                                         uint32_t a3, uint32_t b0, uint32_t b1) {
    asm volatile(
        "mma.sync.aligned.m16n8k16.row.col.f32.bf16.bf16.f32 "
        "{%0,%1,%2,%3},{%4,%5,%6,%7},{%8,%9},{%0,%1,%2,%3};"
        : "+f"(c[0]), "+f"(c[1]), "+f"(c[2]), "+f"(c[3])
        : "r"(a0), "r"(a1), "r"(a2), "r"(a3), "r"(b0), "r"(b1));
}

// SMEM layout: A [split][kchunk(8)][row(128)][32B] = 65536
//              B [split][kchunk(8)][n(128)][32B]   = 65536 (one col-half)
//              stage [128][132 floats]             = 67584
#define SMEM_A 0
#define SMEM_B 65536
#define SMEM_STAGE 131072
#define SMEM_TOTAL (131072 + 67584)
#define STAGE_STRIDE 132

// ---------------- kernel 0: pack B (bf16 hi/lo) + zero cnt -----------------
__global__ __launch_bounds__(256) void pack_kernel(const float* __restrict__ W0,
                                                   const float* __restrict__ W1, int n) {
    int idx = blockIdx.x * 256 + threadIdx.x;
    if (idx < 32768) {
        int k = idx >> 8;          // 0..127
        int c = idx & 255;         // 0..255 global output col
        float v;
        if (c < 128) {
            v = W0[k * 128 + c];
        } else {
            int j = c - 128;
            int h = j >> 5;
            int k2 = j & 31;
            v = W1[(h * 128 + k) * 32 + k2];
        }
        __nv_bfloat16 hi = __float2bfloat16_rn(v);
        __nv_bfloat16 lo = __float2bfloat16_rn(v - __bfloat162float(hi));
        int hf = c >> 7;
        int nn = c & 127;
        int kc = k >> 4;
        int kk = k & 15;
        int base = ((hf * 2 + 0) * 8 + kc) * 4096 + nn * 32 + kk * 2;
        *reinterpret_cast<__nv_bfloat16*>(g_Bpk + base) = hi;
        *reinterpret_cast<__nv_bfloat16*>(g_Bpk + base + 32768) = lo;   // split stride = 8*4096
    }
    if (idx < n) g_cnt[idx] = 0;
}

// ---------------- kernel 1: mma.sync bf16-split GEMM + fused epilogues ------
__global__ __launch_bounds__(256, 1) void gemm_tc_kernel(
    const float* __restrict__ vecs, const float* __restrict__ b0,
    const float* __restrict__ att0, const float* __restrict__ att1,
    const float* __restrict__ attb0, const float* __restrict__ attb1,
    const float* __restrict__ off0, const float* __restrict__ sc0, int n) {
    extern __shared__ __align__(1024) char smem[];
    uint32_t sb = smem_u32(smem);
    float* stage = reinterpret_cast<float*>(smem + SMEM_STAGE);
    int tid = threadIdx.x;
    int wid = tid >> 5;
    int lane = tid & 31;
    int row0 = blockIdx.x * 128;

    int mrow0 = (wid & 3) * 32;          // warp's row block within tile
    int nbase = (wid >> 2) * 64;         // warp's col block within 128-col half

    // lane offsets for ldmatrix (tile t = lane/8)
    int lt = lane >> 3;
    int l7 = lane & 7;
    int alane = ((lt & 1) * 8 + l7) * 32 + (lt >> 1) * 16;   // A: row-major rows, k bytes
    int blane = ((lt >> 1) * 8 + l7) * 32 + (lt & 1) * 16;   // B: n rows, k bytes

    // ---- load A tile: convert fp32 -> bf16 hi/lo into [sp][kc][row][32B] ----
#pragma unroll
    for (int it = 0; it < 16; it++) {
        int t = it * 256 + tid;          // 0..4095
        int r = t >> 5;
        int q = t & 31;                  // float4 index in row
        float4 v = make_float4(0.f, 0.f, 0.f, 0.f);
        int gr = row0 + r;
        if (gr < n) v = __ldg(reinterpret_cast<const float4*>(vecs + (size_t)gr * 128 + q * 4));
        __nv_bfloat16 h0 = __float2bfloat16_rn(v.x), h1 = __float2bfloat16_rn(v.y);
        __nv_bfloat16 h2 = __float2bfloat16_rn(v.z), h3 = __float2bfloat16_rn(v.w);
        __nv_bfloat16 l0 = __float2bfloat16_rn(v.x - __bfloat162float(h0));
        __nv_bfloat16 l1 = __float2bfloat16_rn(v.y - __bfloat162float(h1));
        __nv_bfloat16 l2 = __float2bfloat16_rn(v.z - __bfloat162float(h2));
        __nv_bfloat16 l3 = __float2bfloat16_rn(v.w - __bfloat162float(h3));
        uint2 hv, lv;
        hv.x = ((uint32_t)__bfloat16_as_ushort(h1) << 16) | __bfloat16_as_ushort(h0);
        hv.y = ((uint32_t)__bfloat16_as_ushort(h3) << 16) | __bfloat16_as_ushort(h2);
        lv.x = ((uint32_t)__bfloat16_as_ushort(l1) << 16) | __bfloat16_as_ushort(l0);
        lv.y = ((uint32_t)__bfloat16_as_ushort(l3) << 16) | __bfloat16_as_ushort(l2);
        int kc = q >> 2;
        int kq = q & 3;
        int off = kc * 4096 + r * 32 + kq * 8;
        *reinterpret_cast<uint2*>(smem + SMEM_A + off) = hv;
        *reinterpret_cast<uint2*>(smem + SMEM_A + 32768 + off) = lv;
    }

    // ---- load B half0 (64KB) ----
    {
        const uint4* src = reinterpret_cast<const uint4*>(g_Bpk);
        uint4* dst = reinterpret_cast<uint4*>(smem + SMEM_B);
#pragma unroll
        for (int i = 0; i < 16; i++) dst[tid + i * 256] = __ldg(&src[tid + i * 256]);
    }
    __syncthreads();

    float acc[2][8][4];
    uint32_t Ahi = sb + SMEM_A;
    uint32_t Alo = sb + SMEM_A + 32768;
    uint32_t Bhi = sb + SMEM_B;

    // ================= pass over one col-half ===============================
    auto compute_pass = [&]() {
#pragma unroll
        for (int mt = 0; mt < 2; mt++)
#pragma unroll
            for (int nf = 0; nf < 8; nf++)
#pragma unroll
                for (int q = 0; q < 4; q++) acc[mt][nf][q] = 0.f;
#pragma unroll
        for (int kc = 0; kc < 8; kc++) {
            uint32_t ah[2][4], al[2][4];
#pragma unroll
            for (int mt = 0; mt < 2; mt++) {
                uint32_t aaddr = Ahi + kc * 4096 + (mrow0 + mt * 16) * 32 + alane;
                ldsm4(aaddr, ah[mt][0], ah[mt][1], ah[mt][2], ah[mt][3]);
                ldsm4(aaddr + 32768, al[mt][0], al[mt][1], al[mt][2], al[mt][3]);
            }
#pragma unroll
            for (int np = 0; np < 4; np++) {
                uint32_t bh[4], bl[4];
                uint32_t baddr = Bhi + kc * 4096 + (nbase + np * 16) * 32 + blane;
                ldsm4(baddr, bh[0], bh[1], bh[2], bh[3]);
                ldsm4(baddr + 32768, bl[0], bl[1], bl[2], bl[3]);
#pragma unroll
                for (int mt = 0; mt < 2; mt++)
#pragma unroll
                    for (int j = 0; j < 2; j++) {
                        float* c = acc[mt][np * 2 + j];
                        mma16816(c, ah[mt][0], ah[mt][1], ah[mt][2], ah[mt][3],
                                 bh[2 * j], bh[2 * j + 1]);
                        mma16816(c, ah[mt][0], ah[mt][1], ah[mt][2], ah[mt][3],
                                 bl[2 * j], bl[2 * j + 1]);
                        mma16816(c, al[mt][0], al[mt][1], al[mt][2], al[mt][3],
                                 bh[2 * j], bh[2 * j + 1]);
                    }
            }
        }
    };

    auto stage_accums = [&]() {
#pragma unroll
        for (int mt = 0; mt < 2; mt++)
#pragma unroll
            for (int nf = 0; nf < 8; nf++) {
                int row = mrow0 + mt * 16 + (lane >> 2);
                int col = nbase + nf * 8 + 2 * (lane & 3);
                float* c = acc[mt][nf];
                *reinterpret_cast<float2*>(&stage[row * STAGE_STRIDE + col]) =
                    make_float2(c[0], c[1]);
                *reinterpret_cast<float2*>(&stage[(row + 8) * STAGE_STRIDE + col]) =
                    make_float2(c[2], c[3]);
            }
    };

    // pass 0: cols 0..127 (self path)
    compute_pass();
    __syncthreads();                 // all warps done reading Bbuf half0
    stage_accums();
    {
        const uint4* src = reinterpret_cast<const uint4*>(g_Bpk + 65536);
        uint4* dst = reinterpret_cast<uint4*>(smem + SMEM_B);
#pragma unroll
        for (int i = 0; i < 16; i++) dst[tid + i * 256] = __ldg(&src[tid + i * 256]);
    }
    __syncthreads();                 // stage(pass0) + Bbuf(half1) ready

    // pass 1: cols 128..255 (vw path) — accums stay in regs while we do self epi
    compute_pass();

    // ---- self epilogue: relu+bias, row-norm (reads stage from pass0) -------
    {
        int j = lane << 2;
        float4 bb = __ldg(reinterpret_cast<const float4*>(b0 + j));
        float4 scv = __ldg(reinterpret_cast<const float4*>(sc0 + j));
        float4 ofv = __ldg(reinterpret_cast<const float4*>(off0 + j));
#pragma unroll
        for (int i = 0; i < 16; i++) {
            int r = wid * 16 + i;
            int gr = row0 + r;
            if (gr >= n) break;
            float4 s = *reinterpret_cast<const float4*>(&stage[r * STAGE_STRIDE + j]);
            float t0 = fmaxf(s.x + bb.x, 0.f);
            float t1 = fmaxf(s.y + bb.y, 0.f);
            float t2 = fmaxf(s.z + bb.z, 0.f);
            float t3 = fmaxf(s.w + bb.w, 0.f);
            float sum = t0 + t1 + t2 + t3;
            float sq = t0 * t0 + t1 * t1 + t2 * t2 + t3 * t3;
#pragma unroll
            for (int m = 16; m > 0; m >>= 1) {
                sum += __shfl_xor_sync(0xffffffffu, sum, m);
                sq  += __shfl_xor_sync(0xffffffffu, sq, m);
            }
            float mean = sum * (1.f / 128.f);
            float var = fmaxf(sq * (1.f / 128.f) - mean * mean, 0.f);
            float rs = rsqrtf(var + 1e-9f);
            float4 o;
            o.x = scv.x * (t0 - mean) * rs + ofv.x;
            o.y = scv.y * (t1 - mean) * rs + ofv.y;
            o.z = scv.z * (t2 - mean) * rs + ofv.z;
            o.w = scv.w * (t3 - mean) * rs + ofv.w;
            *reinterpret_cast<float4*>(&g_self[(size_t)gr * 128 + j]) = o;
        }
    }
    __syncthreads();                 // self-epi reads done before overwrite
    stage_accums();
    __syncthreads();

    // ---- vw epilogue: store raw + attention dots ---------------------------
    {
        int j = lane << 2;
        int h = lane >> 3;
        float4 w0v = __ldg(reinterpret_cast<const float4*>(att0 + j));
        float4 w1v = __ldg(reinterpret_cast<const float4*>(att1 + j));
        float ab0 = __ldg(attb0 + h);
        float ab1 = __ldg(attb1 + h);
#pragma unroll
        for (int i = 0; i < 16; i++) {
            int r = wid * 16 + i;
            int gr = row0 + r;
            if (gr >= n) break;
            float4 v = *reinterpret_cast<const float4*>(&stage[r * STAGE_STRIDE + j]);
            *reinterpret_cast<float4*>(&g_vw[(size_t)gr * 128 + j]) = v;
            float d0 = v.x * w0v.x + v.y * w0v.y + v.z * w0v.z + v.w * w0v.w;
            float d1 = v.x * w1v.x + v.y * w1v.y + v.z * w1v.z + v.w * w1v.w;
#pragma unroll
            for (int m = 1; m < 8; m <<= 1) {
                d0 += __shfl_xor_sync(0xffffffffu, d0, m);
                d1 += __shfl_xor_sync(0xffffffffu, d1, m);
            }
            if ((lane & 7) == 0) {
                g_a0[(size_t)gr * 4 + h] = d0 + ab0;
                g_a1[(size_t)gr * 4 + h] = d1 + ab1;
            }
        }
    }
}

// ---------------- kernel 2: histogram of passing edges per dest row --------
__global__ __launch_bounds__(256) void hist_kernel(const float* __restrict__ vals,
                                                   const int* __restrict__ rows,
                                                   const int* __restrict__ cols, int e) {
    int i = blockIdx.x * 256 + threadIdx.x;
    if (i >= e) return;
    int r = __ldg(rows + i);
    int c = __ldg(cols + i);
    float val = __ldg(vals + i);
    float4 ar = __ldg(reinterpret_cast<const float4*>(&g_a0[(size_t)r * 4]));
    float4 ac = __ldg(reinterpret_cast<const float4*>(&g_a1[(size_t)c * 4]));
    float w0 = val * fmaxf(ar.x + ac.x, 0.f);
    float w1 = val * fmaxf(ar.y + ac.y, 0.f);
    float w2 = val * fmaxf(ar.z + ac.z, 0.f);
    float w3 = val * fmaxf(ar.w + ac.w, 0.f);
    if (w0 + w1 + w2 + w3 > 0.f) atomicAdd(&g_cnt[r], 1);
}

// ---------------- scan kernels ----------------------------------------------
__global__ __launch_bounds__(256) void scanA_kernel(int n) {
    int t = threadIdx.x;
    int i = blockIdx.x * 256 + t;
    int v = (i < n) ? g_cnt[i] : 0;
#pragma unroll
    for (int m = 16; m > 0; m >>= 1) v += __shfl_xor_sync(0xffffffffu, v, m);
    __shared__ int ws[8];
    if ((t & 31) == 0) ws[t >> 5] = v;
    __syncthreads();
    if (t == 0) {
        int s = 0;
#pragma unroll
        for (int k = 0; k < 8; k++) s += ws[k];
        g_bsum[blockIdx.x] = s;
    }
}

__global__ __launch_bounds__(512) void scanB_kernel(int nb) {
    __shared__ int s[512];
    int t = threadIdx.x;
    int v = (t < nb) ? g_bsum[t] : 0;
    s[t] = v;
    __syncthreads();
#pragma unroll
    for (int off = 1; off < 512; off <<= 1) {
        int x = (t >= off) ? s[t - off] : 0;
        __syncthreads();
        s[t] += x;
        __syncthreads();
    }
    g_boff[t] = s[t] - v;
}

__global__ __launch_bounds__(256) void scanC_kernel(int n) {
    __shared__ int s[256];
    int t = threadIdx.x;
    int i = blockIdx.x * 256 + t;
    int v = (i < n) ? g_cnt[i] : 0;
    s[t] = v;
    __syncthreads();
#pragma unroll
    for (int off = 1; off < 256; off <<= 1) {
        int x = (t >= off) ? s[t - off] : 0;
        __syncthreads();
        s[t] += x;
        __syncthreads();
    }
    if (i < n) {
        int start = s[t] - v + g_boff[blockIdx.x];
        g_start[i] = start;
        g_cursor[i] = start;
    }
}

// ---------------- kernel 4: scatter compacted edge records ------------------
__global__ __launch_bounds__(256) void scatter_kernel(const float* __restrict__ vals,
                                                      const int* __restrict__ rows,
                                                      const int* __restrict__ cols, int e) {
    int i = blockIdx.x * 256 + threadIdx.x;
    if (i >= e) return;
    int r = __ldg(rows + i);
    int c = __ldg(cols + i);
    float val = __ldg(vals + i);
    float4 ar = __ldg(reinterpret_cast<const float4*>(&g_a0[(size_t)r * 4]));
    float4 ac = __ldg(reinterpret_cast<const float4*>(&g_a1[(size_t)c * 4]));
    float4 w;
    w.x = val * fmaxf(ar.x + ac.x, 0.f);
    w.y = val * fmaxf(ar.y + ac.y, 0.f);
    w.z = val * fmaxf(ar.z + ac.z, 0.f);
    w.w = val * fmaxf(ar.w + ac.w, 0.f);
    if (w.x + w.y + w.z + w.w > 0.f) {
        int pos = atomicAdd(&g_cursor[r], 1);
        g_ecol[pos] = (unsigned int)c;
        g_ew4[pos] = w;
    }
}

// ---------------- kernel 5: per-row aggregation + fused epilogue ------------
__global__ __launch_bounds__(256) void agg_kernel(const float* __restrict__ b1,
                                                  const float* __restrict__ off1,
                                                  const float* __restrict__ sc1,
                                                  float* __restrict__ out, int n) {
    int r = (blockIdx.x << 3) + (threadIdx.x >> 5);
    if (r >= n) return;
    int lane = threadIdx.x & 31;
    int j = lane << 2;
    int h = lane >> 3;

    int start = g_start[r];
    int deg = g_cnt[r];

    float4 acc = make_float4(0.f, 0.f, 0.f, 0.f);
    const float* wbase = reinterpret_cast<const float*>(g_ew4);

    int i = 0;
    for (; i + 4 <= deg; i += 4) {
        unsigned int c0 = __ldg(&g_ecol[start + i + 0]);
        unsigned int c1 = __ldg(&g_ecol[start + i + 1]);
        unsigned int c2 = __ldg(&g_ecol[start + i + 2]);
        unsigned int c3 = __ldg(&g_ecol[start + i + 3]);
        float w0 = __ldg(wbase + (size_t)(start + i + 0) * 4 + h);
        float w1 = __ldg(wbase + (size_t)(start + i + 1) * 4 + h);
        float w2 = __ldg(wbase + (size_t)(start + i + 2) * 4 + h);
        float w3 = __ldg(wbase + (size_t)(start + i + 3) * 4 + h);
        if (w0 > 0.f) {
            float4 v = __ldg(reinterpret_cast<const float4*>(&g_vw[(size_t)c0 * 128 + j]));
            acc.x += w0 * v.x; acc.y += w0 * v.y; acc.z += w0 * v.z; acc.w += w0 * v.w;
        }
        if (w1 > 0.f) {
            float4 v = __ldg(reinterpret_cast<const float4*>(&g_vw[(size_t)c1 * 128 + j]));
            acc.x += w1 * v.x; acc.y += w1 * v.y; acc.z += w1 * v.z; acc.w += w1 * v.w;
        }
        if (w2 > 0.f) {
            float4 v = __ldg(reinterpret_cast<const float4*>(&g_vw[(size_t)c2 * 128 + j]));
            acc.x += w2 * v.x; acc.y += w2 * v.y; acc.z += w2 * v.z; acc.w += w2 * v.w;
        }
        if (w3 > 0.f) {
            float4 v = __ldg(reinterpret_cast<const float4*>(&g_vw[(size_t)c3 * 128 + j]));
            acc.x += w3 * v.x; acc.y += w3 * v.y; acc.z += w3 * v.z; acc.w += w3 * v.w;
        }
    }
    for (; i < deg; i++) {
        unsigned int c = __ldg(&g_ecol[start + i]);
        float w = __ldg(wbase + (size_t)(start + i) * 4 + h);
        if (w > 0.f) {
            float4 v = __ldg(reinterpret_cast<const float4*>(&g_vw[(size_t)c * 128 + j]));
            acc.x += w * v.x; acc.y += w * v.y; acc.z += w * v.z; acc.w += w * v.w;
        }
    }

    float t0 = fmaxf(acc.x, 0.f) + b1[j + 0];
    float t1 = fmaxf(acc.y, 0.f) + b1[j + 1];
    float t2 = fmaxf(acc.z, 0.f) + b1[j + 2];
    float t3 = fmaxf(acc.w, 0.f) + b1[j + 3];
    float sum = t0 + t1 + t2 + t3;
    float sq = t0 * t0 + t1 * t1 + t2 * t2 + t3 * t3;
#pragma unroll
    for (int m = 16; m > 0; m >>= 1) {
        sum += __shfl_xor_sync(0xffffffffu, sum, m);
        sq  += __shfl_xor_sync(0xffffffffu, sq, m);
    }
    float mean = sum * (1.f / 128.f);
    float var = fmaxf(sq * (1.f / 128.f) - mean * mean, 0.f);
    float rs = rsqrtf(var + 1e-9f);
    float4 s = *reinterpret_cast<const float4*>(&g_self[(size_t)r * 128 + j]);
    float4 o;
    o.x = sc1[j + 0] * (t0 - mean) * rs + off1[j + 0] + s.x;
    o.y = sc1[j + 1] * (t1 - mean) * rs + off1[j + 1] + s.y;
    o.z = sc1[j + 2] * (t2 - mean) * rs + off1[j + 2] + s.z;
    o.w = sc1[j + 3] * (t3 - mean) * rs + off1[j + 3] + s.w;
    *reinterpret_cast<float4*>(&out[(size_t)r * 128 + j]) = o;
}

// ---------------- launch ----------------------------------------------------
extern "C" void kernel_launch(void* const* d_in, const int* in_sizes, int n_in,
                              void* d_out, int out_size) {
    const float* vecs     = (const float*)d_in[0];
    const float* adj_vals = (const float*)d_in[1];
    const float* W0       = (const float*)d_in[2];
    const float* b0       = (const float*)d_in[3];
    const float* W1       = (const float*)d_in[4];
    const float* b1       = (const float*)d_in[5];
    const float* att0     = (const float*)d_in[6];
    const float* att1     = (const float*)d_in[7];
    const float* attb0    = (const float*)d_in[8];
    const float* attb1    = (const float*)d_in[9];
    const float* off0     = (const float*)d_in[10];
    const float* sc0      = (const float*)d_in[11];
    const float* off1     = (const float*)d_in[12];
    const float* sc1      = (const float*)d_in[13];
    const int*   rows     = (const int*)d_in[14];
    const int*   cols     = (const int*)d_in[15];

    int n = in_sizes[0] / 128;
    int e = in_sizes[1];
    float* out = (float*)d_out;

    int nb = (n + 255) / 256;
    if (nb < 128) nb = 128;   // pack_kernel also needs 32768 weight threads

    static int smem_set = 0;
    if (!smem_set) {
        cudaFuncSetAttribute(gemm_tc_kernel, cudaFuncAttributeMaxDynamicSharedMemorySize,
                             SMEM_TOTAL);
        smem_set = 1;
    }

    pack_kernel<<<nb, 256>>>(W0, W1, n);
    gemm_tc_kernel<<<(n + 127) / 128, 256, SMEM_TOTAL>>>(vecs, b0, att0, att1, attb0, attb1,
                                                         off0, sc0, n);
    hist_kernel<<<(e + 255) / 256, 256>>>(adj_vals, rows, cols, e);
    scanA_kernel<<<(n + 255) / 256, 256>>>(n);
    scanB_kernel<<<1, 512>>>((n + 255) / 256);
    scanC_kernel<<<(n + 255) / 256, 256>>>(n);
    scatter_kernel<<<(e + 255) / 256, 256>>>(adj_vals, rows, cols, e);
    agg_kernel<<<(n + 7) / 8, 256>>>(b1, off1, sc1, out, n);
}

// round 5
// speedup vs baseline: 1.8454x; 1.1121x over previous
#include <cuda_runtime.h>
#include <cuda_bf16.h>
#include <cuda_fp16.h>
#include <cstdint>

#define MAXN 100000
#define MAXE 1600000

// ---------------- scratch (device globals; no allocation allowed) ----------
// B packed: [half(2)][split(2)][kchunk(8)][n(128)][16 bf16] = 131072 bytes
__device__ __align__(16) uint8_t g_Bpk[131072];
__device__ __align__(16) float  g_self[MAXN * 128];
__device__ __align__(16) __half g_vwh[MAXN * 128];     // fp16 vw for edge gather
__device__ __align__(16) float  g_a0[MAXN * 4];
__device__ __align__(16) float  g_a1[MAXN * 4];
__device__ int   g_cnt[MAXN];
__device__ int   g_start[MAXN];
__device__ int   g_cursor[MAXN];
__device__ int   g_bsum[512];
__device__ int   g_boff[512];
__device__ unsigned int g_ecol[MAXE];
__device__ __align__(16) float4 g_ew4raw[MAXE];        // edge-indexed weights (hist output)
__device__ __align__(16) float4 g_ew4[MAXE];           // compacted per-record weights

// ---------------- helpers ---------------------------------------------------
__device__ __forceinline__ uint32_t smem_u32(const void* p) {
    uint32_t a;
    asm("{ .reg .u64 t; cvta.to.shared.u64 t, %1; cvt.u32.u64 %0, t; }" : "=r"(a) : "l"(p));
    return a;
}
__device__ __forceinline__ void ldsm4(uint32_t addr, uint32_t& r0, uint32_t& r1,
                                      uint32_t& r2, uint32_t& r3) {
    asm volatile("ldmatrix.sync.aligned.m8n8.x4.shared.b16 {%0,%1,%2,%3}, [%4];"
                 : "=r"(r0), "=r"(r1), "=r"(r2), "=r"(r3) : "r"(addr));
}
__device__ __forceinline__ void mma16816(float* c, uint32_t a0, uint32_t a1, uint32_t a2,
                                         uint32_t a3, uint32_t b0, uint32_t b1) {
    asm volatile(
        "mma.sync.aligned.m16n8k16.row.col.f32.bf16.bf16.f32 "
        "{%0,%1,%2,%3},{%4,%5,%6,%7},{%8,%9},{%0,%1,%2,%3};"
        : "+f"(c[0]), "+f"(c[1]), "+f"(c[2]), "+f"(c[3])
        : "r"(a0), "r"(a1), "r"(a2), "r"(a3), "r"(b0), "r"(b1));
}

// SMEM layout: A [split][kchunk(8)][row(128)][32B] = 65536
//              B [split][kchunk(8)][n(128)][32B]   = 65536 (one col-half)
//              stage [128][132 floats]             = 67584
#define SMEM_A 0
#define SMEM_B 65536
#define SMEM_STAGE 131072
#define SMEM_TOTAL (131072 + 67584)
#define STAGE_STRIDE 132

// ---------------- kernel 0: pack B (bf16 hi/lo) + zero cnt -----------------
__global__ __launch_bounds__(256) void pack_kernel(const float* __restrict__ W0,
                                                   const float* __restrict__ W1, int n) {
    int idx = blockIdx.x * 256 + threadIdx.x;
    if (idx < 32768) {
        int k = idx >> 8;          // 0..127
        int c = idx & 255;         // 0..255 global output col
        float v;
        if (c < 128) {
            v = W0[k * 128 + c];
        } else {
            int j = c - 128;
            int h = j >> 5;
            int k2 = j & 31;
            v = W1[(h * 128 + k) * 32 + k2];
        }
        __nv_bfloat16 hi = __float2bfloat16_rn(v);
        __nv_bfloat16 lo = __float2bfloat16_rn(v - __bfloat162float(hi));
        int hf = c >> 7;
        int nn = c & 127;
        int kc = k >> 4;
        int kk = k & 15;
        int base = ((hf * 2 + 0) * 8 + kc) * 4096 + nn * 32 + kk * 2;
        *reinterpret_cast<__nv_bfloat16*>(g_Bpk + base) = hi;
        *reinterpret_cast<__nv_bfloat16*>(g_Bpk + base + 32768) = lo;   // split stride = 8*4096
    }
    if (idx < n) g_cnt[idx] = 0;
}

// ---------------- kernel 1: mma.sync bf16-split GEMM + fused epilogues ------
__global__ __launch_bounds__(256, 1) void gemm_tc_kernel(
    const float* __restrict__ vecs, const float* __restrict__ b0,
    const float* __restrict__ att0, const float* __restrict__ att1,
    const float* __restrict__ attb0, const float* __restrict__ attb1,
    const float* __restrict__ off0, const float* __restrict__ sc0, int n) {
    extern __shared__ __align__(1024) char smem[];
    uint32_t sb = smem_u32(smem);
    float* stage = reinterpret_cast<float*>(smem + SMEM_STAGE);
    int tid = threadIdx.x;
    int wid = tid >> 5;
    int lane = tid & 31;
    int row0 = blockIdx.x * 128;

    int mrow0 = (wid & 3) * 32;
    int nbase = (wid >> 2) * 64;

    int lt = lane >> 3;
    int l7 = lane & 7;
    int alane = ((lt & 1) * 8 + l7) * 32 + (lt >> 1) * 16;
    int blane = ((lt >> 1) * 8 + l7) * 32 + (lt & 1) * 16;

    // ---- load A tile: convert fp32 -> bf16 hi/lo into [sp][kc][row][32B] ----
#pragma unroll
    for (int it = 0; it < 16; it++) {
        int t = it * 256 + tid;
        int r = t >> 5;
        int q = t & 31;
        float4 v = make_float4(0.f, 0.f, 0.f, 0.f);
        int gr = row0 + r;
        if (gr < n) v = __ldg(reinterpret_cast<const float4*>(vecs + (size_t)gr * 128 + q * 4));
        __nv_bfloat16 h0 = __float2bfloat16_rn(v.x), h1 = __float2bfloat16_rn(v.y);
        __nv_bfloat16 h2 = __float2bfloat16_rn(v.z), h3 = __float2bfloat16_rn(v.w);
        __nv_bfloat16 l0 = __float2bfloat16_rn(v.x - __bfloat162float(h0));
        __nv_bfloat16 l1 = __float2bfloat16_rn(v.y - __bfloat162float(h1));
        __nv_bfloat16 l2 = __float2bfloat16_rn(v.z - __bfloat162float(h2));
        __nv_bfloat16 l3 = __float2bfloat16_rn(v.w - __bfloat162float(h3));
        uint2 hv, lv;
        hv.x = ((uint32_t)__bfloat16_as_ushort(h1) << 16) | __bfloat16_as_ushort(h0);
        hv.y = ((uint32_t)__bfloat16_as_ushort(h3) << 16) | __bfloat16_as_ushort(h2);
        lv.x = ((uint32_t)__bfloat16_as_ushort(l1) << 16) | __bfloat16_as_ushort(l0);
        lv.y = ((uint32_t)__bfloat16_as_ushort(l3) << 16) | __bfloat16_as_ushort(l2);
        int kc = q >> 2;
        int kq = q & 3;
        int off = kc * 4096 + r * 32 + kq * 8;
        *reinterpret_cast<uint2*>(smem + SMEM_A + off) = hv;
        *reinterpret_cast<uint2*>(smem + SMEM_A + 32768 + off) = lv;
    }

    // ---- load B half0 (64KB) ----
    {
        const uint4* src = reinterpret_cast<const uint4*>(g_Bpk);
        uint4* dst = reinterpret_cast<uint4*>(smem + SMEM_B);
#pragma unroll
        for (int i = 0; i < 16; i++) dst[tid + i * 256] = __ldg(&src[tid + i * 256]);
    }
    __syncthreads();

    float acc[2][8][4];
    uint32_t Ahi = sb + SMEM_A;
    uint32_t Bhi = sb + SMEM_B;

    auto compute_pass = [&]() {
#pragma unroll
        for (int mt = 0; mt < 2; mt++)
#pragma unroll
            for (int nf = 0; nf < 8; nf++)
#pragma unroll
                for (int q = 0; q < 4; q++) acc[mt][nf][q] = 0.f;
#pragma unroll
        for (int kc = 0; kc < 8; kc++) {
            uint32_t ah[2][4], al[2][4];
#pragma unroll
            for (int mt = 0; mt < 2; mt++) {
                uint32_t aaddr = Ahi + kc * 4096 + (mrow0 + mt * 16) * 32 + alane;
                ldsm4(aaddr, ah[mt][0], ah[mt][1], ah[mt][2], ah[mt][3]);
                ldsm4(aaddr + 32768, al[mt][0], al[mt][1], al[mt][2], al[mt][3]);
            }
#pragma unroll
            for (int np = 0; np < 4; np++) {
                uint32_t bh[4], bl[4];
                uint32_t baddr = Bhi + kc * 4096 + (nbase + np * 16) * 32 + blane;
                ldsm4(baddr, bh[0], bh[1], bh[2], bh[3]);
                ldsm4(baddr + 32768, bl[0], bl[1], bl[2], bl[3]);
#pragma unroll
                for (int mt = 0; mt < 2; mt++)
#pragma unroll
                    for (int j = 0; j < 2; j++) {
                        float* c = acc[mt][np * 2 + j];
                        mma16816(c, ah[mt][0], ah[mt][1], ah[mt][2], ah[mt][3],
                                 bh[2 * j], bh[2 * j + 1]);
                        mma16816(c, ah[mt][0], ah[mt][1], ah[mt][2], ah[mt][3],
                                 bl[2 * j], bl[2 * j + 1]);
                        mma16816(c, al[mt][0], al[mt][1], al[mt][2], al[mt][3],
                                 bh[2 * j], bh[2 * j + 1]);
                    }
            }
        }
    };

    auto stage_accums = [&]() {
#pragma unroll
        for (int mt = 0; mt < 2; mt++)
#pragma unroll
            for (int nf = 0; nf < 8; nf++) {
                int row = mrow0 + mt * 16 + (lane >> 2);
                int col = nbase + nf * 8 + 2 * (lane & 3);
                float* c = acc[mt][nf];
                *reinterpret_cast<float2*>(&stage[row * STAGE_STRIDE + col]) =
                    make_float2(c[0], c[1]);
                *reinterpret_cast<float2*>(&stage[(row + 8) * STAGE_STRIDE + col]) =
                    make_float2(c[2], c[3]);
            }
    };

    // pass 0: cols 0..127 (self path)
    compute_pass();
    __syncthreads();
    stage_accums();
    {
        const uint4* src = reinterpret_cast<const uint4*>(g_Bpk + 65536);
        uint4* dst = reinterpret_cast<uint4*>(smem + SMEM_B);
#pragma unroll
        for (int i = 0; i < 16; i++) dst[tid + i * 256] = __ldg(&src[tid + i * 256]);
    }
    __syncthreads();

    // pass 1: cols 128..255 (vw path)
    compute_pass();

    // ---- self epilogue: relu+bias, row-norm (reads stage from pass0) -------
    {
        int j = lane << 2;
        float4 bb = __ldg(reinterpret_cast<const float4*>(b0 + j));
        float4 scv = __ldg(reinterpret_cast<const float4*>(sc0 + j));
        float4 ofv = __ldg(reinterpret_cast<const float4*>(off0 + j));
#pragma unroll
        for (int i = 0; i < 16; i++) {
            int r = wid * 16 + i;
            int gr = row0 + r;
            if (gr >= n) break;
            float4 s = *reinterpret_cast<const float4*>(&stage[r * STAGE_STRIDE + j]);
            float t0 = fmaxf(s.x + bb.x, 0.f);
            float t1 = fmaxf(s.y + bb.y, 0.f);
            float t2 = fmaxf(s.z + bb.z, 0.f);
            float t3 = fmaxf(s.w + bb.w, 0.f);
            float sum = t0 + t1 + t2 + t3;
            float sq = t0 * t0 + t1 * t1 + t2 * t2 + t3 * t3;
#pragma unroll
            for (int m = 16; m > 0; m >>= 1) {
                sum += __shfl_xor_sync(0xffffffffu, sum, m);
                sq  += __shfl_xor_sync(0xffffffffu, sq, m);
            }
            float mean = sum * (1.f / 128.f);
            float var = fmaxf(sq * (1.f / 128.f) - mean * mean, 0.f);
            float rs = rsqrtf(var + 1e-9f);
            float4 o;
            o.x = scv.x * (t0 - mean) * rs + ofv.x;
            o.y = scv.y * (t1 - mean) * rs + ofv.y;
            o.z = scv.z * (t2 - mean) * rs + ofv.z;
            o.w = scv.w * (t3 - mean) * rs + ofv.w;
            *reinterpret_cast<float4*>(&g_self[(size_t)gr * 128 + j]) = o;
        }
    }
    __syncthreads();
    stage_accums();
    __syncthreads();

    // ---- vw epilogue: store fp16 + attention dots --------------------------
    {
        int j = lane << 2;
        int h = lane >> 3;
        float4 w0v = __ldg(reinterpret_cast<const float4*>(att0 + j));
        float4 w1v = __ldg(reinterpret_cast<const float4*>(att1 + j));
        float ab0 = __ldg(attb0 + h);
        float ab1 = __ldg(attb1 + h);
#pragma unroll
        for (int i = 0; i < 16; i++) {
            int r = wid * 16 + i;
            int gr = row0 + r;
            if (gr >= n) break;
            float4 v = *reinterpret_cast<const float4*>(&stage[r * STAGE_STRIDE + j]);
            __half2 p0 = __floats2half2_rn(v.x, v.y);
            __half2 p1 = __floats2half2_rn(v.z, v.w);
            uint2 pk;
            pk.x = *reinterpret_cast<uint32_t*>(&p0);
            pk.y = *reinterpret_cast<uint32_t*>(&p1);
            *reinterpret_cast<uint2*>(&g_vwh[(size_t)gr * 128 + j]) = pk;
            float d0 = v.x * w0v.x + v.y * w0v.y + v.z * w0v.z + v.w * w0v.w;
            float d1 = v.x * w1v.x + v.y * w1v.y + v.z * w1v.z + v.w * w1v.w;
#pragma unroll
            for (int m = 1; m < 8; m <<= 1) {
                d0 += __shfl_xor_sync(0xffffffffu, d0, m);
                d1 += __shfl_xor_sync(0xffffffffu, d1, m);
            }
            if ((lane & 7) == 0) {
                g_a0[(size_t)gr * 4 + h] = d0 + ab0;
                g_a1[(size_t)gr * 4 + h] = d1 + ab1;
            }
        }
    }
}

// ---------------- kernel 2: hist + cache per-edge weights -------------------
__global__ __launch_bounds__(256) void hist_kernel(const float* __restrict__ vals,
                                                   const int* __restrict__ rows,
                                                   const int* __restrict__ cols, int e) {
    int i = blockIdx.x * 256 + threadIdx.x;
    if (i >= e) return;
    int r = __ldg(rows + i);
    int c = __ldg(cols + i);
    float val = __ldg(vals + i);
    float4 ar = __ldg(reinterpret_cast<const float4*>(&g_a0[(size_t)r * 4]));
    float4 ac = __ldg(reinterpret_cast<const float4*>(&g_a1[(size_t)c * 4]));
    float4 w;
    w.x = val * fmaxf(ar.x + ac.x, 0.f);
    w.y = val * fmaxf(ar.y + ac.y, 0.f);
    w.z = val * fmaxf(ar.z + ac.z, 0.f);
    w.w = val * fmaxf(ar.w + ac.w, 0.f);
    g_ew4raw[i] = w;
    if (w.x + w.y + w.z + w.w > 0.f) atomicAdd(&g_cnt[r], 1);
}

// ---------------- scan kernels ----------------------------------------------
__global__ __launch_bounds__(256) void scanA_kernel(int n) {
    int t = threadIdx.x;
    int i = blockIdx.x * 256 + t;
    int v = (i < n) ? g_cnt[i] : 0;
#pragma unroll
    for (int m = 16; m > 0; m >>= 1) v += __shfl_xor_sync(0xffffffffu, v, m);
    __shared__ int ws[8];
    if ((t & 31) == 0) ws[t >> 5] = v;
    __syncthreads();
    if (t == 0) {
        int s = 0;
#pragma unroll
        for (int k = 0; k < 8; k++) s += ws[k];
        g_bsum[blockIdx.x] = s;
    }
}

__global__ __launch_bounds__(512) void scanB_kernel(int nb) {
    __shared__ int s[512];
    int t = threadIdx.x;
    int v = (t < nb) ? g_bsum[t] : 0;
    s[t] = v;
    __syncthreads();
#pragma unroll
    for (int off = 1; off < 512; off <<= 1) {
        int x = (t >= off) ? s[t - off] : 0;
        __syncthreads();
        s[t] += x;
        __syncthreads();
    }
    g_boff[t] = s[t] - v;
}

__global__ __launch_bounds__(256) void scanC_kernel(int n) {
    __shared__ int s[256];
    int t = threadIdx.x;
    int i = blockIdx.x * 256 + t;
    int v = (i < n) ? g_cnt[i] : 0;
    s[t] = v;
    __syncthreads();
#pragma unroll
    for (int off = 1; off < 256; off <<= 1) {
        int x = (t >= off) ? s[t - off] : 0;
        __syncthreads();
        s[t] += x;
        __syncthreads();
    }
    if (i < n) {
        int start = s[t] - v + g_boff[blockIdx.x];
        g_start[i] = start;
        g_cursor[i] = start;
    }
}

// ---------------- kernel 4: scatter compacted edge records ------------------
__global__ __launch_bounds__(256) void scatter_kernel(const int* __restrict__ rows,
                                                      const int* __restrict__ cols, int e) {
    int i = blockIdx.x * 256 + threadIdx.x;
    if (i >= e) return;
    float4 w = __ldg(reinterpret_cast<const float4*>(&g_ew4raw[i]));
    if (w.x + w.y + w.z + w.w > 0.f) {
        int r = __ldg(rows + i);
        int c = __ldg(cols + i);
        int pos = atomicAdd(&g_cursor[r], 1);
        g_ecol[pos] = (unsigned int)c;
        g_ew4[pos] = w;
    }
}

// ---------------- kernel 5: per-row aggregation + fused epilogue ------------
__global__ __launch_bounds__(256) void agg_kernel(const float* __restrict__ b1,
                                                  const float* __restrict__ off1,
                                                  const float* __restrict__ sc1,
                                                  float* __restrict__ out, int n) {
    int r = (blockIdx.x << 3) + (threadIdx.x >> 5);
    if (r >= n) return;
    int lane = threadIdx.x & 31;
    int j = lane << 2;
    int h = lane >> 3;

    int start = g_start[r];
    int deg = g_cnt[r];

    float4 acc = make_float4(0.f, 0.f, 0.f, 0.f);
    const float* wbase = reinterpret_cast<const float*>(g_ew4);

    auto gather = [&](unsigned int c, float w) {
        uint2 pk = __ldg(reinterpret_cast<const uint2*>(&g_vwh[(size_t)c * 128 + j]));
        float2 v0 = __half22float2(*reinterpret_cast<__half2*>(&pk.x));
        float2 v1 = __half22float2(*reinterpret_cast<__half2*>(&pk.y));
        acc.x += w * v0.x;
        acc.y += w * v0.y;
        acc.z += w * v1.x;
        acc.w += w * v1.y;
    };

    int i = 0;
    for (; i + 4 <= deg; i += 4) {
        unsigned int c0 = __ldg(&g_ecol[start + i + 0]);
        unsigned int c1 = __ldg(&g_ecol[start + i + 1]);
        unsigned int c2 = __ldg(&g_ecol[start + i + 2]);
        unsigned int c3 = __ldg(&g_ecol[start + i + 3]);
        float w0 = __ldg(wbase + (size_t)(start + i + 0) * 4 + h);
        float w1 = __ldg(wbase + (size_t)(start + i + 1) * 4 + h);
        float w2 = __ldg(wbase + (size_t)(start + i + 2) * 4 + h);
        float w3 = __ldg(wbase + (size_t)(start + i + 3) * 4 + h);
        if (w0 > 0.f) gather(c0, w0);
        if (w1 > 0.f) gather(c1, w1);
        if (w2 > 0.f) gather(c2, w2);
        if (w3 > 0.f) gather(c3, w3);
    }
    for (; i < deg; i++) {
        unsigned int c = __ldg(&g_ecol[start + i]);
        float w = __ldg(wbase + (size_t)(start + i) * 4 + h);
        if (w > 0.f) gather(c, w);
    }

    float t0 = fmaxf(acc.x, 0.f) + b1[j + 0];
    float t1 = fmaxf(acc.y, 0.f) + b1[j + 1];
    float t2 = fmaxf(acc.z, 0.f) + b1[j + 2];
    float t3 = fmaxf(acc.w, 0.f) + b1[j + 3];
    float sum = t0 + t1 + t2 + t3;
    float sq = t0 * t0 + t1 * t1 + t2 * t2 + t3 * t3;
#pragma unroll
    for (int m = 16; m > 0; m >>= 1) {
        sum += __shfl_xor_sync(0xffffffffu, sum, m);
        sq  += __shfl_xor_sync(0xffffffffu, sq, m);
    }
    float mean = sum * (1.f / 128.f);
    float var = fmaxf(sq * (1.f / 128.f) - mean * mean, 0.f);
    float rs = rsqrtf(var + 1e-9f);
    float4 s = *reinterpret_cast<const float4*>(&g_self[(size_t)r * 128 + j]);
    float4 o;
    o.x = sc1[j + 0] * (t0 - mean) * rs + off1[j + 0] + s.x;
    o.y = sc1[j + 1] * (t1 - mean) * rs + off1[j + 1] + s.y;
    o.z = sc1[j + 2] * (t2 - mean) * rs + off1[j + 2] + s.z;
    o.w = sc1[j + 3] * (t3 - mean) * rs + off1[j + 3] + s.w;
    *reinterpret_cast<float4*>(&out[(size_t)r * 128 + j]) = o;
}

// ---------------- launch ----------------------------------------------------
extern "C" void kernel_launch(void* const* d_in, const int* in_sizes, int n_in,
                              void* d_out, int out_size) {
    const float* vecs     = (const float*)d_in[0];
    const float* adj_vals = (const float*)d_in[1];
    const float* W0       = (const float*)d_in[2];
    const float* b0       = (const float*)d_in[3];
    const float* W1       = (const float*)d_in[4];
    const float* b1       = (const float*)d_in[5];
    const float* att0     = (const float*)d_in[6];
    const float* att1     = (const float*)d_in[7];
    const float* attb0    = (const float*)d_in[8];
    const float* attb1    = (const float*)d_in[9];
    const float* off0     = (const float*)d_in[10];
    const float* sc0      = (const float*)d_in[11];
    const float* off1     = (const float*)d_in[12];
    const float* sc1      = (const float*)d_in[13];
    const int*   rows     = (const int*)d_in[14];
    const int*   cols     = (const int*)d_in[15];

    int n = in_sizes[0] / 128;
    int e = in_sizes[1];
    float* out = (float*)d_out;

    int nb = (n + 255) / 256;
    int nbp = nb < 128 ? 128 : nb;   // pack_kernel also needs 32768 weight threads

    static int smem_set = 0;
    if (!smem_set) {
        cudaFuncSetAttribute(gemm_tc_kernel, cudaFuncAttributeMaxDynamicSharedMemorySize,
                             SMEM_TOTAL);
        smem_set = 1;
    }

    pack_kernel<<<nbp, 256>>>(W0, W1, n);
    gemm_tc_kernel<<<(n + 127) / 128, 256, SMEM_TOTAL>>>(vecs, b0, att0, att1, attb0, attb1,
                                                         off0, sc0, n);
    hist_kernel<<<(e + 255) / 256, 256>>>(adj_vals, rows, cols, e);
    scanA_kernel<<<nb, 256>>>(n);
    scanB_kernel<<<1, 512>>>(nb);
    scanC_kernel<<<nb, 256>>>(n);
    scatter_kernel<<<(e + 255) / 256, 256>>>(rows, cols, e);
    agg_kernel<<<(n + 7) / 8, 256>>>(b1, off1, sc1, out, n);
}

// round 6
// speedup vs baseline: 1.9372x; 1.0497x over previous
#include <cuda_runtime.h>
#include <cuda_bf16.h>
#include <cuda_fp16.h>
#include <cstdint>

#define MAXN 100000
#define MAXE 1600000

// ---------------- scratch (device globals; no allocation allowed) ----------
// B packed: [half(2)][split(2)][kchunk(8)][n(128)][16 bf16] = 131072 bytes
__device__ __align__(16) uint8_t g_Bpk[131072];
__device__ __align__(16) float  g_self[MAXN * 128];
__device__ __align__(16) __half g_vwh[MAXN * 128];     // fp16 vw for edge gather
__device__ __align__(16) float  g_a0[MAXN * 4];
__device__ __align__(16) float  g_a1[MAXN * 4];
__device__ int   g_cnt[MAXN];                          // FULL degree per dest row
__device__ int   g_start[MAXN];
__device__ int   g_cursor[MAXN];
__device__ int   g_bsum[512];
__device__ int   g_boff[512];
__device__ unsigned int g_ecol[MAXE];
__device__ __align__(8) __half g_ewh[MAXE * 4];        // compacted per-record fp16 weights

// ---------------- helpers ---------------------------------------------------
__device__ __forceinline__ uint32_t smem_u32(const void* p) {
    uint32_t a;
    asm("{ .reg .u64 t; cvta.to.shared.u64 t, %1; cvt.u32.u64 %0, t; }" : "=r"(a) : "l"(p));
    return a;
}
__device__ __forceinline__ void ldsm4(uint32_t addr, uint32_t& r0, uint32_t& r1,
                                      uint32_t& r2, uint32_t& r3) {
    asm volatile("ldmatrix.sync.aligned.m8n8.x4.shared.b16 {%0,%1,%2,%3}, [%4];"
                 : "=r"(r0), "=r"(r1), "=r"(r2), "=r"(r3) : "r"(addr));
}
__device__ __forceinline__ void mma16816(float* c, uint32_t a0, uint32_t a1, uint32_t a2,
                                         uint32_t a3, uint32_t b0, uint32_t b1) {
    asm volatile(
        "mma.sync.aligned.m16n8k16.row.col.f32.bf16.bf16.f32 "
        "{%0,%1,%2,%3},{%4,%5,%6,%7},{%8,%9},{%0,%1,%2,%3};"
        : "+f"(c[0]), "+f"(c[1]), "+f"(c[2]), "+f"(c[3])
        : "r"(a0), "r"(a1), "r"(a2), "r"(a3), "r"(b0), "r"(b1));
}

// SMEM layout: A [split][kchunk(8)][row(128)][32B] = 65536
//              B [split][kchunk(8)][n(128)][32B]   = 65536 (one col-half)
//              stage [128][132 floats]             = 67584
#define SMEM_A 0
#define SMEM_B 65536
#define SMEM_STAGE 131072
#define SMEM_TOTAL (131072 + 67584)
#define STAGE_STRIDE 132

// ---------------- kernel 0: pack B (bf16 hi/lo) + zero cnt -----------------
__global__ __launch_bounds__(256) void pack_kernel(const float* __restrict__ W0,
                                                   const float* __restrict__ W1, int n) {
    int idx = blockIdx.x * 256 + threadIdx.x;
    if (idx < 32768) {
        int k = idx >> 8;          // 0..127
        int c = idx & 255;         // 0..255 global output col
        float v;
        if (c < 128) {
            v = W0[k * 128 + c];
        } else {
            int j = c - 128;
            int h = j >> 5;
            int k2 = j & 31;
            v = W1[(h * 128 + k) * 32 + k2];
        }
        __nv_bfloat16 hi = __float2bfloat16_rn(v);
        __nv_bfloat16 lo = __float2bfloat16_rn(v - __bfloat162float(hi));
        int hf = c >> 7;
        int nn = c & 127;
        int kc = k >> 4;
        int kk = k & 15;
        int base = ((hf * 2 + 0) * 8 + kc) * 4096 + nn * 32 + kk * 2;
        *reinterpret_cast<__nv_bfloat16*>(g_Bpk + base) = hi;
        *reinterpret_cast<__nv_bfloat16*>(g_Bpk + base + 32768) = lo;   // split stride = 8*4096
    }
    if (idx < n) g_cnt[idx] = 0;
}

// ---------------- kernel 1: mma.sync bf16-split GEMM + fused epilogues ------
__global__ __launch_bounds__(256, 1) void gemm_tc_kernel(
    const float* __restrict__ vecs, const float* __restrict__ b0,
    const float* __restrict__ att0, const float* __restrict__ att1,
    const float* __restrict__ attb0, const float* __restrict__ attb1,
    const float* __restrict__ off0, const float* __restrict__ sc0, int n) {
    extern __shared__ __align__(1024) char smem[];
    uint32_t sb = smem_u32(smem);
    float* stage = reinterpret_cast<float*>(smem + SMEM_STAGE);
    int tid = threadIdx.x;
    int wid = tid >> 5;
    int lane = tid & 31;
    int row0 = blockIdx.x * 128;

    int mrow0 = (wid & 3) * 32;
    int nbase = (wid >> 2) * 64;

    int lt = lane >> 3;
    int l7 = lane & 7;
    int alane = ((lt & 1) * 8 + l7) * 32 + (lt >> 1) * 16;
    int blane = ((lt >> 1) * 8 + l7) * 32 + (lt & 1) * 16;

    // ---- load A tile: convert fp32 -> bf16 hi/lo into [sp][kc][row][32B] ----
#pragma unroll
    for (int it = 0; it < 16; it++) {
        int t = it * 256 + tid;
        int r = t >> 5;
        int q = t & 31;
        float4 v = make_float4(0.f, 0.f, 0.f, 0.f);
        int gr = row0 + r;
        if (gr < n) v = __ldg(reinterpret_cast<const float4*>(vecs + (size_t)gr * 128 + q * 4));
        __nv_bfloat16 h0 = __float2bfloat16_rn(v.x), h1 = __float2bfloat16_rn(v.y);
        __nv_bfloat16 h2 = __float2bfloat16_rn(v.z), h3 = __float2bfloat16_rn(v.w);
        __nv_bfloat16 l0 = __float2bfloat16_rn(v.x - __bfloat162float(h0));
        __nv_bfloat16 l1 = __float2bfloat16_rn(v.y - __bfloat162float(h1));
        __nv_bfloat16 l2 = __float2bfloat16_rn(v.z - __bfloat162float(h2));
        __nv_bfloat16 l3 = __float2bfloat16_rn(v.w - __bfloat162float(h3));
        uint2 hv, lv;
        hv.x = ((uint32_t)__bfloat16_as_ushort(h1) << 16) | __bfloat16_as_ushort(h0);
        hv.y = ((uint32_t)__bfloat16_as_ushort(h3) << 16) | __bfloat16_as_ushort(h2);
        lv.x = ((uint32_t)__bfloat16_as_ushort(l1) << 16) | __bfloat16_as_ushort(l0);
        lv.y = ((uint32_t)__bfloat16_as_ushort(l3) << 16) | __bfloat16_as_ushort(l2);
        int kc = q >> 2;
        int kq = q & 3;
        int off = kc * 4096 + r * 32 + kq * 8;
        *reinterpret_cast<uint2*>(smem + SMEM_A + off) = hv;
        *reinterpret_cast<uint2*>(smem + SMEM_A + 32768 + off) = lv;
    }

    // ---- load B half0 (64KB) ----
    {
        const uint4* src = reinterpret_cast<const uint4*>(g_Bpk);
        uint4* dst = reinterpret_cast<uint4*>(smem + SMEM_B);
#pragma unroll
        for (int i = 0; i < 16; i++) dst[tid + i * 256] = __ldg(&src[tid + i * 256]);
    }
    __syncthreads();

    float acc[2][8][4];
    uint32_t Ahi = sb + SMEM_A;
    uint32_t Bhi = sb + SMEM_B;

    auto compute_pass = [&]() {
#pragma unroll
        for (int mt = 0; mt < 2; mt++)
#pragma unroll
            for (int nf = 0; nf < 8; nf++)
#pragma unroll
                for (int q = 0; q < 4; q++) acc[mt][nf][q] = 0.f;
#pragma unroll
        for (int kc = 0; kc < 8; kc++) {
            uint32_t ah[2][4], al[2][4];
#pragma unroll
            for (int mt = 0; mt < 2; mt++) {
                uint32_t aaddr = Ahi + kc * 4096 + (mrow0 + mt * 16) * 32 + alane;
                ldsm4(aaddr, ah[mt][0], ah[mt][1], ah[mt][2], ah[mt][3]);
                ldsm4(aaddr + 32768, al[mt][0], al[mt][1], al[mt][2], al[mt][3]);
            }
#pragma unroll
            for (int np = 0; np < 4; np++) {
                uint32_t bh[4], bl[4];
                uint32_t baddr = Bhi + kc * 4096 + (nbase + np * 16) * 32 + blane;
                ldsm4(baddr, bh[0], bh[1], bh[2], bh[3]);
                ldsm4(baddr + 32768, bl[0], bl[1], bl[2], bl[3]);
#pragma unroll
                for (int mt = 0; mt < 2; mt++)
#pragma unroll
                    for (int j = 0; j < 2; j++) {
                        float* c = acc[mt][np * 2 + j];
                        mma16816(c, ah[mt][0], ah[mt][1], ah[mt][2], ah[mt][3],
                                 bh[2 * j], bh[2 * j + 1]);
                        mma16816(c, ah[mt][0], ah[mt][1], ah[mt][2], ah[mt][3],
                                 bl[2 * j], bl[2 * j + 1]);
                        mma16816(c, al[mt][0], al[mt][1], al[mt][2], al[mt][3],
                                 bh[2 * j], bh[2 * j + 1]);
                    }
            }
        }
    };

    auto stage_accums = [&]() {
#pragma unroll
        for (int mt = 0; mt < 2; mt++)
#pragma unroll
            for (int nf = 0; nf < 8; nf++) {
                int row = mrow0 + mt * 16 + (lane >> 2);
                int col = nbase + nf * 8 + 2 * (lane & 3);
                float* c = acc[mt][nf];
                *reinterpret_cast<float2*>(&stage[row * STAGE_STRIDE + col]) =
                    make_float2(c[0], c[1]);
                *reinterpret_cast<float2*>(&stage[(row + 8) * STAGE_STRIDE + col]) =
                    make_float2(c[2], c[3]);
            }
    };

    // pass 0: cols 0..127 (self path)
    compute_pass();
    __syncthreads();
    stage_accums();
    {
        const uint4* src = reinterpret_cast<const uint4*>(g_Bpk + 65536);
        uint4* dst = reinterpret_cast<uint4*>(smem + SMEM_B);
#pragma unroll
        for (int i = 0; i < 16; i++) dst[tid + i * 256] = __ldg(&src[tid + i * 256]);
    }
    __syncthreads();

    // pass 1: cols 128..255 (vw path)
    compute_pass();

    // ---- self epilogue: relu+bias, row-norm (reads stage from pass0) -------
    {
        int j = lane << 2;
        float4 bb = __ldg(reinterpret_cast<const float4*>(b0 + j));
        float4 scv = __ldg(reinterpret_cast<const float4*>(sc0 + j));
        float4 ofv = __ldg(reinterpret_cast<const float4*>(off0 + j));
#pragma unroll
        for (int i = 0; i < 16; i++) {
            int r = wid * 16 + i;
            int gr = row0 + r;
            if (gr >= n) break;
            float4 s = *reinterpret_cast<const float4*>(&stage[r * STAGE_STRIDE + j]);
            float t0 = fmaxf(s.x + bb.x, 0.f);
            float t1 = fmaxf(s.y + bb.y, 0.f);
            float t2 = fmaxf(s.z + bb.z, 0.f);
            float t3 = fmaxf(s.w + bb.w, 0.f);
            float sum = t0 + t1 + t2 + t3;
            float sq = t0 * t0 + t1 * t1 + t2 * t2 + t3 * t3;
#pragma unroll
            for (int m = 16; m > 0; m >>= 1) {
                sum += __shfl_xor_sync(0xffffffffu, sum, m);
                sq  += __shfl_xor_sync(0xffffffffu, sq, m);
            }
            float mean = sum * (1.f / 128.f);
            float var = fmaxf(sq * (1.f / 128.f) - mean * mean, 0.f);
            float rs = rsqrtf(var + 1e-9f);
            float4 o;
            o.x = scv.x * (t0 - mean) * rs + ofv.x;
            o.y = scv.y * (t1 - mean) * rs + ofv.y;
            o.z = scv.z * (t2 - mean) * rs + ofv.z;
            o.w = scv.w * (t3 - mean) * rs + ofv.w;
            *reinterpret_cast<float4*>(&g_self[(size_t)gr * 128 + j]) = o;
        }
    }
    __syncthreads();
    stage_accums();
    __syncthreads();

    // ---- vw epilogue: store fp16 + attention dots --------------------------
    {
        int j = lane << 2;
        int h = lane >> 3;
        float4 w0v = __ldg(reinterpret_cast<const float4*>(att0 + j));
        float4 w1v = __ldg(reinterpret_cast<const float4*>(att1 + j));
        float ab0 = __ldg(attb0 + h);
        float ab1 = __ldg(attb1 + h);
#pragma unroll
        for (int i = 0; i < 16; i++) {
            int r = wid * 16 + i;
            int gr = row0 + r;
            if (gr >= n) break;
            float4 v = *reinterpret_cast<const float4*>(&stage[r * STAGE_STRIDE + j]);
            __half2 p0 = __floats2half2_rn(v.x, v.y);
            __half2 p1 = __floats2half2_rn(v.z, v.w);
            uint2 pk;
            pk.x = *reinterpret_cast<uint32_t*>(&p0);
            pk.y = *reinterpret_cast<uint32_t*>(&p1);
            *reinterpret_cast<uint2*>(&g_vwh[(size_t)gr * 128 + j]) = pk;
            float d0 = v.x * w0v.x + v.y * w0v.y + v.z * w0v.z + v.w * w0v.w;
            float d1 = v.x * w1v.x + v.y * w1v.y + v.z * w1v.z + v.w * w1v.w;
#pragma unroll
            for (int m = 1; m < 8; m <<= 1) {
                d0 += __shfl_xor_sync(0xffffffffu, d0, m);
                d1 += __shfl_xor_sync(0xffffffffu, d1, m);
            }
            if ((lane & 7) == 0) {
                g_a0[(size_t)gr * 4 + h] = d0 + ab0;
                g_a1[(size_t)gr * 4 + h] = d1 + ab1;
            }
        }
    }
}

// ---------------- kernel 2: full-degree histogram (no attention needed) ----
__global__ __launch_bounds__(256) void hist_kernel(const int* __restrict__ rows, int e) {
    int i = blockIdx.x * 256 + threadIdx.x;
    if (i >= e) return;
    atomicAdd(&g_cnt[__ldg(rows + i)], 1);
}

// ---------------- scan kernels ----------------------------------------------
__global__ __launch_bounds__(256) void scanA_kernel(int n) {
    int t = threadIdx.x;
    int i = blockIdx.x * 256 + t;
    int v = (i < n) ? g_cnt[i] : 0;
#pragma unroll
    for (int m = 16; m > 0; m >>= 1) v += __shfl_xor_sync(0xffffffffu, v, m);
    __shared__ int ws[8];
    if ((t & 31) == 0) ws[t >> 5] = v;
    __syncthreads();
    if (t == 0) {
        int s = 0;
#pragma unroll
        for (int k = 0; k < 8; k++) s += ws[k];
        g_bsum[blockIdx.x] = s;
    }
}

__global__ __launch_bounds__(512) void scanB_kernel(int nb) {
    __shared__ int s[512];
    int t = threadIdx.x;
    int v = (t < nb) ? g_bsum[t] : 0;
    s[t] = v;
    __syncthreads();
#pragma unroll
    for (int off = 1; off < 512; off <<= 1) {
        int x = (t >= off) ? s[t - off] : 0;
        __syncthreads();
        s[t] += x;
        __syncthreads();
    }
    g_boff[t] = s[t] - v;
}

__global__ __launch_bounds__(256) void scanC_kernel(int n) {
    __shared__ int s[256];
    int t = threadIdx.x;
    int i = blockIdx.x * 256 + t;
    int v = (i < n) ? g_cnt[i] : 0;
    s[t] = v;
    __syncthreads();
#pragma unroll
    for (int off = 1; off < 256; off <<= 1) {
        int x = (t >= off) ? s[t - off] : 0;
        __syncthreads();
        s[t] += x;
        __syncthreads();
    }
    if (i < n) {
        int start = s[t] - v + g_boff[blockIdx.x];
        g_start[i] = start;
        g_cursor[i] = start;
    }
}

// ---------------- kernel 3: compute weights, filter, compact ----------------
__global__ __launch_bounds__(256) void scatter_kernel(const float* __restrict__ vals,
                                                      const int* __restrict__ rows,
                                                      const int* __restrict__ cols, int e) {
    int i = blockIdx.x * 256 + threadIdx.x;
    if (i >= e) return;
    int r = __ldg(rows + i);
    int c = __ldg(cols + i);
    float val = __ldg(vals + i);
    float4 ar = __ldg(reinterpret_cast<const float4*>(&g_a0[(size_t)r * 4]));
    float4 ac = __ldg(reinterpret_cast<const float4*>(&g_a1[(size_t)c * 4]));
    float w0 = val * fmaxf(ar.x + ac.x, 0.f);
    float w1 = val * fmaxf(ar.y + ac.y, 0.f);
    float w2 = val * fmaxf(ar.z + ac.z, 0.f);
    float w3 = val * fmaxf(ar.w + ac.w, 0.f);
    if (w0 + w1 + w2 + w3 > 0.f) {
        int pos = atomicAdd(&g_cursor[r], 1);
        g_ecol[pos] = (unsigned int)c;
        __half2 p0 = __floats2half2_rn(w0, w1);
        __half2 p1 = __floats2half2_rn(w2, w3);
        uint2 pk;
        pk.x = *reinterpret_cast<uint32_t*>(&p0);
        pk.y = *reinterpret_cast<uint32_t*>(&p1);
        *reinterpret_cast<uint2*>(&g_ewh[(size_t)pos * 4]) = pk;
    }
}

// ---------------- kernel 4: per-row aggregation + fused epilogue ------------
__global__ __launch_bounds__(256) void agg_kernel(const float* __restrict__ b1,
                                                  const float* __restrict__ off1,
                                                  const float* __restrict__ sc1,
                                                  float* __restrict__ out, int n) {
    int r = (blockIdx.x << 3) + (threadIdx.x >> 5);
    if (r >= n) return;
    int lane = threadIdx.x & 31;
    int j = lane << 2;
    int h = lane >> 3;

    int start = g_start[r];
    int deg = g_cursor[r] - start;   // passing-edge count

    float4 acc = make_float4(0.f, 0.f, 0.f, 0.f);

    auto gather = [&](unsigned int c, float w) {
        uint2 pk = __ldg(reinterpret_cast<const uint2*>(&g_vwh[(size_t)c * 128 + j]));
        float2 v0 = __half22float2(*reinterpret_cast<__half2*>(&pk.x));
        float2 v1 = __half22float2(*reinterpret_cast<__half2*>(&pk.y));
        acc.x += w * v0.x;
        acc.y += w * v0.y;
        acc.z += w * v1.x;
        acc.w += w * v1.y;
    };

    int i = 0;
    for (; i + 4 <= deg; i += 4) {
        unsigned int c0 = __ldg(&g_ecol[start + i + 0]);
        unsigned int c1 = __ldg(&g_ecol[start + i + 1]);
        unsigned int c2 = __ldg(&g_ecol[start + i + 2]);
        unsigned int c3 = __ldg(&g_ecol[start + i + 3]);
        float w0 = __half2float(__ldg(&g_ewh[(size_t)(start + i + 0) * 4 + h]));
        float w1 = __half2float(__ldg(&g_ewh[(size_t)(start + i + 1) * 4 + h]));
        float w2 = __half2float(__ldg(&g_ewh[(size_t)(start + i + 2) * 4 + h]));
        float w3 = __half2float(__ldg(&g_ewh[(size_t)(start + i + 3) * 4 + h]));
        if (w0 > 0.f) gather(c0, w0);
        if (w1 > 0.f) gather(c1, w1);
        if (w2 > 0.f) gather(c2, w2);
        if (w3 > 0.f) gather(c3, w3);
    }
    for (; i < deg; i++) {
        unsigned int c = __ldg(&g_ecol[start + i]);
        float w = __half2float(__ldg(&g_ewh[(size_t)(start + i) * 4 + h]));
        if (w > 0.f) gather(c, w);
    }

    float t0 = fmaxf(acc.x, 0.f) + b1[j + 0];
    float t1 = fmaxf(acc.y, 0.f) + b1[j + 1];
    float t2 = fmaxf(acc.z, 0.f) + b1[j + 2];
    float t3 = fmaxf(acc.w, 0.f) + b1[j + 3];
    float sum = t0 + t1 + t2 + t3;
    float sq = t0 * t0 + t1 * t1 + t2 * t2 + t3 * t3;
#pragma unroll
    for (int m = 16; m > 0; m >>= 1) {
        sum += __shfl_xor_sync(0xffffffffu, sum, m);
        sq  += __shfl_xor_sync(0xffffffffu, sq, m);
    }
    float mean = sum * (1.f / 128.f);
    float var = fmaxf(sq * (1.f / 128.f) - mean * mean, 0.f);
    float rs = rsqrtf(var + 1e-9f);
    float4 s = *reinterpret_cast<const float4*>(&g_self[(size_t)r * 128 + j]);
    float4 o;
    o.x = sc1[j + 0] * (t0 - mean) * rs + off1[j + 0] + s.x;
    o.y = sc1[j + 1] * (t1 - mean) * rs + off1[j + 1] + s.y;
    o.z = sc1[j + 2] * (t2 - mean) * rs + off1[j + 2] + s.z;
    o.w = sc1[j + 3] * (t3 - mean) * rs + off1[j + 3] + s.w;
    *reinterpret_cast<float4*>(&out[(size_t)r * 128 + j]) = o;
}

// ---------------- launch ----------------------------------------------------
extern "C" void kernel_launch(void* const* d_in, const int* in_sizes, int n_in,
                              void* d_out, int out_size) {
    const float* vecs     = (const float*)d_in[0];
    const float* adj_vals = (const float*)d_in[1];
    const float* W0       = (const float*)d_in[2];
    const float* b0       = (const float*)d_in[3];
    const float* W1       = (const float*)d_in[4];
    const float* b1       = (const float*)d_in[5];
    const float* att0     = (const float*)d_in[6];
    const float* att1     = (const float*)d_in[7];
    const float* attb0    = (const float*)d_in[8];
    const float* attb1    = (const float*)d_in[9];
    const float* off0     = (const float*)d_in[10];
    const float* sc0      = (const float*)d_in[11];
    const float* off1     = (const float*)d_in[12];
    const float* sc1      = (const float*)d_in[13];
    const int*   rows     = (const int*)d_in[14];
    const int*   cols     = (const int*)d_in[15];

    int n = in_sizes[0] / 128;
    int e = in_sizes[1];
    float* out = (float*)d_out;

    int nb = (n + 255) / 256;
    int nbp = nb < 128 ? 128 : nb;   // pack_kernel also needs 32768 weight threads

    static int smem_set = 0;
    if (!smem_set) {
        cudaFuncSetAttribute(gemm_tc_kernel, cudaFuncAttributeMaxDynamicSharedMemorySize,
                             SMEM_TOTAL);
        smem_set = 1;
    }

    pack_kernel<<<nbp, 256>>>(W0, W1, n);
    hist_kernel<<<(e + 255) / 256, 256>>>(rows, e);        // independent of gemm
    gemm_tc_kernel<<<(n + 127) / 128, 256, SMEM_TOTAL>>>(vecs, b0, att0, att1, attb0, attb1,
                                                         off0, sc0, n);
    scanA_kernel<<<nb, 256>>>(n);
    scanB_kernel<<<1, 512>>>(nb);
    scanC_kernel<<<nb, 256>>>(n);
    scatter_kernel<<<(e + 255) / 256, 256>>>(adj_vals, rows, cols, e);
    agg_kernel<<<(n + 7) / 8, 256>>>(b1, off1, sc1, out, n);
}

// round 7
// speedup vs baseline: 2.0161x; 1.0407x over previous
#include <cuda_runtime.h>
#include <cuda_bf16.h>
#include <cuda_fp16.h>
#include <cstdint>

#define MAXN 100000
#define MAXE 1600000

// ---------------- scratch (device globals; no allocation allowed) ----------
// B packed: [half(2)][split(2)][kchunk(8)][n(128)][16 bf16] = 131072 bytes
__device__ __align__(16) uint8_t g_Bpk[131072];
__device__ __align__(16) float  g_self[MAXN * 128];
__device__ __align__(16) __half g_vwh[MAXN * 128];     // fp16 vw for edge gather
__device__ __align__(16) float  g_a0[MAXN * 4];
__device__ __align__(16) float  g_a1[MAXN * 4];
__device__ int   g_cnt[MAXN];                          // FULL degree per dest row
__device__ int   g_start[MAXN];
__device__ int   g_cursor[MAXN];
__device__ int   g_ticket;                             // scan tile ticket
__device__ volatile unsigned int g_state[512];         // (status<<30)|sum
__device__ unsigned int g_ecol[MAXE];
__device__ __align__(8) __half g_ewh[MAXE * 4];        // compacted per-record fp16 weights

// ---------------- helpers ---------------------------------------------------
__device__ __forceinline__ uint32_t smem_u32(const void* p) {
    uint32_t a;
    asm("{ .reg .u64 t; cvta.to.shared.u64 t, %1; cvt.u32.u64 %0, t; }" : "=r"(a) : "l"(p));
    return a;
}
__device__ __forceinline__ void ldsm4(uint32_t addr, uint32_t& r0, uint32_t& r1,
                                      uint32_t& r2, uint32_t& r3) {
    asm volatile("ldmatrix.sync.aligned.m8n8.x4.shared.b16 {%0,%1,%2,%3}, [%4];"
                 : "=r"(r0), "=r"(r1), "=r"(r2), "=r"(r3) : "r"(addr));
}
__device__ __forceinline__ void mma16816(float* c, uint32_t a0, uint32_t a1, uint32_t a2,
                                         uint32_t a3, uint32_t b0, uint32_t b1) {
    asm volatile(
        "mma.sync.aligned.m16n8k16.row.col.f32.bf16.bf16.f32 "
        "{%0,%1,%2,%3},{%4,%5,%6,%7},{%8,%9},{%0,%1,%2,%3};"
        : "+f"(c[0]), "+f"(c[1]), "+f"(c[2]), "+f"(c[3])
        : "r"(a0), "r"(a1), "r"(a2), "r"(a3), "r"(b0), "r"(b1));
}

// SMEM layout: A [split][kchunk(8)][row(128)][32B] = 65536
//              B [split][kchunk(8)][n(128)][32B]   = 65536 (one col-half)
//              stage [128][132 floats]             = 67584
#define SMEM_A 0
#define SMEM_B 65536
#define SMEM_STAGE 131072
#define SMEM_TOTAL (131072 + 67584)
#define STAGE_STRIDE 132

// ---------------- kernel 0: pack B (bf16 hi/lo) + zero cnt/scan state ------
__global__ __launch_bounds__(256) void pack_kernel(const float* __restrict__ W0,
                                                   const float* __restrict__ W1, int n) {
    int idx = blockIdx.x * 256 + threadIdx.x;
    if (idx < 32768) {
        int k = idx >> 8;          // 0..127
        int c = idx & 255;         // 0..255 global output col
        float v;
        if (c < 128) {
            v = W0[k * 128 + c];
        } else {
            int j = c - 128;
            int h = j >> 5;
            int k2 = j & 31;
            v = W1[(h * 128 + k) * 32 + k2];
        }
        __nv_bfloat16 hi = __float2bfloat16_rn(v);
        __nv_bfloat16 lo = __float2bfloat16_rn(v - __bfloat162float(hi));
        int hf = c >> 7;
        int nn = c & 127;
        int kc = k >> 4;
        int kk = k & 15;
        int base = ((hf * 2 + 0) * 8 + kc) * 4096 + nn * 32 + kk * 2;
        *reinterpret_cast<__nv_bfloat16*>(g_Bpk + base) = hi;
        *reinterpret_cast<__nv_bfloat16*>(g_Bpk + base + 32768) = lo;   // split stride = 8*4096
    }
    if (idx < n) g_cnt[idx] = 0;
    if (idx < 512) g_state[idx] = 0;
    if (idx == 0) g_ticket = 0;
}

// ---------------- kernel 1: mma.sync bf16-split GEMM + fused epilogues ------
__global__ __launch_bounds__(256, 1) void gemm_tc_kernel(
    const float* __restrict__ vecs, const float* __restrict__ b0,
    const float* __restrict__ att0, const float* __restrict__ att1,
    const float* __restrict__ attb0, const float* __restrict__ attb1,
    const float* __restrict__ off0, const float* __restrict__ sc0, int n) {
    extern __shared__ __align__(1024) char smem[];
    uint32_t sb = smem_u32(smem);
    float* stage = reinterpret_cast<float*>(smem + SMEM_STAGE);
    int tid = threadIdx.x;
    int wid = tid >> 5;
    int lane = tid & 31;
    int row0 = blockIdx.x * 128;

    int mrow0 = (wid & 3) * 32;
    int nbase = (wid >> 2) * 64;

    int lt = lane >> 3;
    int l7 = lane & 7;
    int alane = ((lt & 1) * 8 + l7) * 32 + (lt >> 1) * 16;
    int blane = ((lt >> 1) * 8 + l7) * 32 + (lt & 1) * 16;

    // ---- load A tile: convert fp32 -> bf16 hi/lo into [sp][kc][row][32B] ----
#pragma unroll
    for (int it = 0; it < 16; it++) {
        int t = it * 256 + tid;
        int r = t >> 5;
        int q = t & 31;
        float4 v = make_float4(0.f, 0.f, 0.f, 0.f);
        int gr = row0 + r;
        if (gr < n) v = __ldg(reinterpret_cast<const float4*>(vecs + (size_t)gr * 128 + q * 4));
        __nv_bfloat16 h0 = __float2bfloat16_rn(v.x), h1 = __float2bfloat16_rn(v.y);
        __nv_bfloat16 h2 = __float2bfloat16_rn(v.z), h3 = __float2bfloat16_rn(v.w);
        __nv_bfloat16 l0 = __float2bfloat16_rn(v.x - __bfloat162float(h0));
        __nv_bfloat16 l1 = __float2bfloat16_rn(v.y - __bfloat162float(h1));
        __nv_bfloat16 l2 = __float2bfloat16_rn(v.z - __bfloat162float(h2));
        __nv_bfloat16 l3 = __float2bfloat16_rn(v.w - __bfloat162float(h3));
        uint2 hv, lv;
        hv.x = ((uint32_t)__bfloat16_as_ushort(h1) << 16) | __bfloat16_as_ushort(h0);
        hv.y = ((uint32_t)__bfloat16_as_ushort(h3) << 16) | __bfloat16_as_ushort(h2);
        lv.x = ((uint32_t)__bfloat16_as_ushort(l1) << 16) | __bfloat16_as_ushort(l0);
        lv.y = ((uint32_t)__bfloat16_as_ushort(l3) << 16) | __bfloat16_as_ushort(l2);
        int kc = q >> 2;
        int kq = q & 3;
        int off = kc * 4096 + r * 32 + kq * 8;
        *reinterpret_cast<uint2*>(smem + SMEM_A + off) = hv;
        *reinterpret_cast<uint2*>(smem + SMEM_A + 32768 + off) = lv;
    }

    // ---- load B half0 (64KB) ----
    {
        const uint4* src = reinterpret_cast<const uint4*>(g_Bpk);
        uint4* dst = reinterpret_cast<uint4*>(smem + SMEM_B);
#pragma unroll
        for (int i = 0; i < 16; i++) dst[tid + i * 256] = __ldg(&src[tid + i * 256]);
    }
    __syncthreads();

    float acc[2][8][4];
    uint32_t Ahi = sb + SMEM_A;
    uint32_t Bhi = sb + SMEM_B;

    auto compute_pass = [&]() {
#pragma unroll
        for (int mt = 0; mt < 2; mt++)
#pragma unroll
            for (int nf = 0; nf < 8; nf++)
#pragma unroll
                for (int q = 0; q < 4; q++) acc[mt][nf][q] = 0.f;
#pragma unroll
        for (int kc = 0; kc < 8; kc++) {
            uint32_t ah[2][4], al[2][4];
#pragma unroll
            for (int mt = 0; mt < 2; mt++) {
                uint32_t aaddr = Ahi + kc * 4096 + (mrow0 + mt * 16) * 32 + alane;
                ldsm4(aaddr, ah[mt][0], ah[mt][1], ah[mt][2], ah[mt][3]);
                ldsm4(aaddr + 32768, al[mt][0], al[mt][1], al[mt][2], al[mt][3]);
            }
#pragma unroll
            for (int np = 0; np < 4; np++) {
                uint32_t bh[4], bl[4];
                uint32_t baddr = Bhi + kc * 4096 + (nbase + np * 16) * 32 + blane;
                ldsm4(baddr, bh[0], bh[1], bh[2], bh[3]);
                ldsm4(baddr + 32768, bl[0], bl[1], bl[2], bl[3]);
#pragma unroll
                for (int mt = 0; mt < 2; mt++)
#pragma unroll
                    for (int j = 0; j < 2; j++) {
                        float* c = acc[mt][np * 2 + j];
                        mma16816(c, ah[mt][0], ah[mt][1], ah[mt][2], ah[mt][3],
                                 bh[2 * j], bh[2 * j + 1]);
                        mma16816(c, ah[mt][0], ah[mt][1], ah[mt][2], ah[mt][3],
                                 bl[2 * j], bl[2 * j + 1]);
                        mma16816(c, al[mt][0], al[mt][1], al[mt][2], al[mt][3],
                                 bh[2 * j], bh[2 * j + 1]);
                    }
            }
        }
    };

    auto stage_accums = [&]() {
#pragma unroll
        for (int mt = 0; mt < 2; mt++)
#pragma unroll
            for (int nf = 0; nf < 8; nf++) {
                int row = mrow0 + mt * 16 + (lane >> 2);
                int col = nbase + nf * 8 + 2 * (lane & 3);
                float* c = acc[mt][nf];
                *reinterpret_cast<float2*>(&stage[row * STAGE_STRIDE + col]) =
                    make_float2(c[0], c[1]);
                *reinterpret_cast<float2*>(&stage[(row + 8) * STAGE_STRIDE + col]) =
                    make_float2(c[2], c[3]);
            }
    };

    // pass 0: cols 0..127 (self path)
    compute_pass();
    __syncthreads();
    stage_accums();
    {
        const uint4* src = reinterpret_cast<const uint4*>(g_Bpk + 65536);
        uint4* dst = reinterpret_cast<uint4*>(smem + SMEM_B);
#pragma unroll
        for (int i = 0; i < 16; i++) dst[tid + i * 256] = __ldg(&src[tid + i * 256]);
    }
    __syncthreads();

    // pass 1: cols 128..255 (vw path)
    compute_pass();

    // ---- self epilogue: relu+bias, row-norm (reads stage from pass0) -------
    {
        int j = lane << 2;
        float4 bb = __ldg(reinterpret_cast<const float4*>(b0 + j));
        float4 scv = __ldg(reinterpret_cast<const float4*>(sc0 + j));
        float4 ofv = __ldg(reinterpret_cast<const float4*>(off0 + j));
#pragma unroll
        for (int i = 0; i < 16; i++) {
            int r = wid * 16 + i;
            int gr = row0 + r;
            if (gr >= n) break;
            float4 s = *reinterpret_cast<const float4*>(&stage[r * STAGE_STRIDE + j]);
            float t0 = fmaxf(s.x + bb.x, 0.f);
            float t1 = fmaxf(s.y + bb.y, 0.f);
            float t2 = fmaxf(s.z + bb.z, 0.f);
            float t3 = fmaxf(s.w + bb.w, 0.f);
            float sum = t0 + t1 + t2 + t3;
            float sq = t0 * t0 + t1 * t1 + t2 * t2 + t3 * t3;
#pragma unroll
            for (int m = 16; m > 0; m >>= 1) {
                sum += __shfl_xor_sync(0xffffffffu, sum, m);
                sq  += __shfl_xor_sync(0xffffffffu, sq, m);
            }
            float mean = sum * (1.f / 128.f);
            float var = fmaxf(sq * (1.f / 128.f) - mean * mean, 0.f);
            float rs = rsqrtf(var + 1e-9f);
            float4 o;
            o.x = scv.x * (t0 - mean) * rs + ofv.x;
            o.y = scv.y * (t1 - mean) * rs + ofv.y;
            o.z = scv.z * (t2 - mean) * rs + ofv.z;
            o.w = scv.w * (t3 - mean) * rs + ofv.w;
            *reinterpret_cast<float4*>(&g_self[(size_t)gr * 128 + j]) = o;
        }
    }
    __syncthreads();
    stage_accums();
    __syncthreads();

    // ---- vw epilogue: store fp16 + attention dots --------------------------
    {
        int j = lane << 2;
        int h = lane >> 3;
        float4 w0v = __ldg(reinterpret_cast<const float4*>(att0 + j));
        float4 w1v = __ldg(reinterpret_cast<const float4*>(att1 + j));
        float ab0 = __ldg(attb0 + h);
        float ab1 = __ldg(attb1 + h);
#pragma unroll
        for (int i = 0; i < 16; i++) {
            int r = wid * 16 + i;
            int gr = row0 + r;
            if (gr >= n) break;
            float4 v = *reinterpret_cast<const float4*>(&stage[r * STAGE_STRIDE + j]);
            __half2 p0 = __floats2half2_rn(v.x, v.y);
            __half2 p1 = __floats2half2_rn(v.z, v.w);
            uint2 pk;
            pk.x = *reinterpret_cast<uint32_t*>(&p0);
            pk.y = *reinterpret_cast<uint32_t*>(&p1);
            *reinterpret_cast<uint2*>(&g_vwh[(size_t)gr * 128 + j]) = pk;
            float d0 = v.x * w0v.x + v.y * w0v.y + v.z * w0v.z + v.w * w0v.w;
            float d1 = v.x * w1v.x + v.y * w1v.y + v.z * w1v.z + v.w * w1v.w;
#pragma unroll
            for (int m = 1; m < 8; m <<= 1) {
                d0 += __shfl_xor_sync(0xffffffffu, d0, m);
                d1 += __shfl_xor_sync(0xffffffffu, d1, m);
            }
            if ((lane & 7) == 0) {
                g_a0[(size_t)gr * 4 + h] = d0 + ab0;
                g_a1[(size_t)gr * 4 + h] = d1 + ab1;
            }
        }
    }
}

// ---------------- kernel 2: full-degree histogram ----------------------------
__global__ __launch_bounds__(256) void hist_kernel(const int* __restrict__ rows, int e) {
    int i = blockIdx.x * 256 + threadIdx.x;
    if (i >= e) return;
    atomicAdd(&g_cnt[__ldg(rows + i)], 1);
}

// ---------------- kernel 3: single-pass decoupled-lookback scan -------------
__global__ __launch_bounds__(256) void scan_kernel(int n) {
    __shared__ int s_bid;
    __shared__ int s_wsum[8];
    __shared__ int s_prefix;
    int tid = threadIdx.x;
    int wid = tid >> 5;
    int lane = tid & 31;

    if (tid == 0) s_bid = atomicAdd(&g_ticket, 1);
    __syncthreads();
    int bid = s_bid;

    int i = bid * 256 + tid;
    int v = (i < n) ? g_cnt[i] : 0;

    // block-inclusive scan
    int incl = v;
#pragma unroll
    for (int m = 1; m < 32; m <<= 1) {
        int x = __shfl_up_sync(0xffffffffu, incl, m);
        if (lane >= m) incl += x;
    }
    if (lane == 31) s_wsum[wid] = incl;
    __syncthreads();
    if (wid == 0 && lane < 8) {
        int w = s_wsum[lane];
#pragma unroll
        for (int m = 1; m < 8; m <<= 1) {
            int x = __shfl_up_sync(0xffu, w, m);
            if (lane >= m) w += x;
        }
        s_wsum[lane] = w;
    }
    __syncthreads();
    int blocksum = s_wsum[7];
    if (wid > 0) incl += s_wsum[wid - 1];

    // publish aggregate (or inclusive if bid 0)
    if (tid == 0) {
        unsigned int tag = (bid == 0) ? ((2u << 30) | (unsigned int)blocksum)
                                      : ((1u << 30) | (unsigned int)blocksum);
        g_state[bid] = tag;
        __threadfence();
    }

    // warp 0: lookback
    if (wid == 0) {
        int prefix = 0;
        if (bid > 0) {
            int look = bid - 1;
            while (true) {
                int idx2 = look - lane;
                unsigned int st;
                if (idx2 < 0) {
                    st = (2u << 30);
                } else {
                    do { st = g_state[idx2]; } while ((st >> 30) == 0u);
                }
                unsigned int status = st >> 30;
                int val = (int)(st & 0x3FFFFFFFu);
                unsigned int ball = __ballot_sync(0xffffffffu, status >= 2u);
                if (ball) {
                    int first = __ffs(ball) - 1;       // nearest predecessor w/ inclusive
                    int contrib = (lane <= first) ? val : 0;
#pragma unroll
                    for (int m = 16; m > 0; m >>= 1)
                        contrib += __shfl_xor_sync(0xffffffffu, contrib, m);
                    prefix += contrib;
                    break;
                } else {
                    int contrib = val;
#pragma unroll
                    for (int m = 16; m > 0; m >>= 1)
                        contrib += __shfl_xor_sync(0xffffffffu, contrib, m);
                    prefix += contrib;
                    look -= 32;
                }
            }
            if (lane == 0) {
                g_state[bid] = (2u << 30) | (unsigned int)(prefix + blocksum);
                __threadfence();
            }
        }
        if (lane == 0) s_prefix = prefix;
    }
    __syncthreads();

    if (i < n) {
        int start = s_prefix + incl - v;   // exclusive prefix
        g_start[i] = start;
        g_cursor[i] = start;
    }
}

// ---------------- kernel 4: compute weights, filter, compact ----------------
__global__ __launch_bounds__(256) void scatter_kernel(const float* __restrict__ vals,
                                                      const int* __restrict__ rows,
                                                      const int* __restrict__ cols, int e) {
    int i = blockIdx.x * 256 + threadIdx.x;
    if (i >= e) return;
    int r = __ldg(rows + i);
    int c = __ldg(cols + i);
    float val = __ldg(vals + i);
    float4 ar = __ldg(reinterpret_cast<const float4*>(&g_a0[(size_t)r * 4]));
    float4 ac = __ldg(reinterpret_cast<const float4*>(&g_a1[(size_t)c * 4]));
    float w0 = val * fmaxf(ar.x + ac.x, 0.f);
    float w1 = val * fmaxf(ar.y + ac.y, 0.f);
    float w2 = val * fmaxf(ar.z + ac.z, 0.f);
    float w3 = val * fmaxf(ar.w + ac.w, 0.f);
    if (w0 + w1 + w2 + w3 > 0.f) {
        int pos = atomicAdd(&g_cursor[r], 1);
        g_ecol[pos] = (unsigned int)c;
        __half2 p0 = __floats2half2_rn(w0, w1);
        __half2 p1 = __floats2half2_rn(w2, w3);
        uint2 pk;
        pk.x = *reinterpret_cast<uint32_t*>(&p0);
        pk.y = *reinterpret_cast<uint32_t*>(&p1);
        *reinterpret_cast<uint2*>(&g_ewh[(size_t)pos * 4]) = pk;
    }
}

// ---------------- kernel 5: per-row aggregation + fused epilogue ------------
__global__ __launch_bounds__(256) void agg_kernel(const float* __restrict__ b1,
                                                  const float* __restrict__ off1,
                                                  const float* __restrict__ sc1,
                                                  float* __restrict__ out, int n) {
    int r = (blockIdx.x << 3) + (threadIdx.x >> 5);
    if (r >= n) return;
    int lane = threadIdx.x & 31;
    int j = lane << 2;
    int h = lane >> 3;

    int start = g_start[r];
    int deg = g_cursor[r] - start;   // passing-edge count

    float4 acc = make_float4(0.f, 0.f, 0.f, 0.f);

    auto gather = [&](unsigned int c, float w) {
        uint2 pk = __ldg(reinterpret_cast<const uint2*>(&g_vwh[(size_t)c * 128 + j]));
        float2 v0 = __half22float2(*reinterpret_cast<__half2*>(&pk.x));
        float2 v1 = __half22float2(*reinterpret_cast<__half2*>(&pk.y));
        acc.x += w * v0.x;
        acc.y += w * v0.y;
        acc.z += w * v1.x;
        acc.w += w * v1.y;
    };

    int i = 0;
    for (; i + 4 <= deg; i += 4) {
        unsigned int c0 = __ldg(&g_ecol[start + i + 0]);
        unsigned int c1 = __ldg(&g_ecol[start + i + 1]);
        unsigned int c2 = __ldg(&g_ecol[start + i + 2]);
        unsigned int c3 = __ldg(&g_ecol[start + i + 3]);
        float w0 = __half2float(__ldg(&g_ewh[(size_t)(start + i + 0) * 4 + h]));
        float w1 = __half2float(__ldg(&g_ewh[(size_t)(start + i + 1) * 4 + h]));
        float w2 = __half2float(__ldg(&g_ewh[(size_t)(start + i + 2) * 4 + h]));
        float w3 = __half2float(__ldg(&g_ewh[(size_t)(start + i + 3) * 4 + h]));
        if (w0 > 0.f) gather(c0, w0);
        if (w1 > 0.f) gather(c1, w1);
        if (w2 > 0.f) gather(c2, w2);
        if (w3 > 0.f) gather(c3, w3);
    }
    for (; i < deg; i++) {
        unsigned int c = __ldg(&g_ecol[start + i]);
        float w = __half2float(__ldg(&g_ewh[(size_t)(start + i) * 4 + h]));
        if (w > 0.f) gather(c, w);
    }

    float t0 = fmaxf(acc.x, 0.f) + b1[j + 0];
    float t1 = fmaxf(acc.y, 0.f) + b1[j + 1];
    float t2 = fmaxf(acc.z, 0.f) + b1[j + 2];
    float t3 = fmaxf(acc.w, 0.f) + b1[j + 3];
    float sum = t0 + t1 + t2 + t3;
    float sq = t0 * t0 + t1 * t1 + t2 * t2 + t3 * t3;
#pragma unroll
    for (int m = 16; m > 0; m >>= 1) {
        sum += __shfl_xor_sync(0xffffffffu, sum, m);
        sq  += __shfl_xor_sync(0xffffffffu, sq, m);
    }
    float mean = sum * (1.f / 128.f);
    float var = fmaxf(sq * (1.f / 128.f) - mean * mean, 0.f);
    float rs = rsqrtf(var + 1e-9f);
    float4 s = *reinterpret_cast<const float4*>(&g_self[(size_t)r * 128 + j]);
    float4 o;
    o.x = sc1[j + 0] * (t0 - mean) * rs + off1[j + 0] + s.x;
    o.y = sc1[j + 1] * (t1 - mean) * rs + off1[j + 1] + s.y;
    o.z = sc1[j + 2] * (t2 - mean) * rs + off1[j + 2] + s.z;
    o.w = sc1[j + 3] * (t3 - mean) * rs + off1[j + 3] + s.w;
    *reinterpret_cast<float4*>(&out[(size_t)r * 128 + j]) = o;
}

// ---------------- launch ----------------------------------------------------
extern "C" void kernel_launch(void* const* d_in, const int* in_sizes, int n_in,
                              void* d_out, int out_size) {
    const float* vecs     = (const float*)d_in[0];
    const float* adj_vals = (const float*)d_in[1];
    const float* W0       = (const float*)d_in[2];
    const float* b0       = (const float*)d_in[3];
    const float* W1       = (const float*)d_in[4];
    const float* b1       = (const float*)d_in[5];
    const float* att0     = (const float*)d_in[6];
    const float* att1     = (const float*)d_in[7];
    const float* attb0    = (const float*)d_in[8];
    const float* attb1    = (const float*)d_in[9];
    const float* off0     = (const float*)d_in[10];
    const float* sc0      = (const float*)d_in[11];
    const float* off1     = (const float*)d_in[12];
    const float* sc1      = (const float*)d_in[13];
    const int*   rows     = (const int*)d_in[14];
    const int*   cols     = (const int*)d_in[15];

    int n = in_sizes[0] / 128;
    int e = in_sizes[1];
    float* out = (float*)d_out;

    int nb = (n + 255) / 256;
    int nbp = nb < 128 ? 128 : nb;   // pack_kernel also needs 32768 weight threads

    static cudaStream_t s2 = nullptr;
    static cudaEvent_t ev_fork = nullptr, ev_join = nullptr;
    static int smem_set = 0;
    if (!smem_set) {
        cudaFuncSetAttribute(gemm_tc_kernel, cudaFuncAttributeMaxDynamicSharedMemorySize,
                             SMEM_TOTAL);
        cudaStreamCreateWithFlags(&s2, cudaStreamNonBlocking);
        cudaEventCreateWithFlags(&ev_fork, cudaEventDisableTiming);
        cudaEventCreateWithFlags(&ev_join, cudaEventDisableTiming);
        smem_set = 1;
    }

    // main stream: pack, then fork
    pack_kernel<<<nbp, 256>>>(W0, W1, n);
    cudaEventRecord(ev_fork, 0);
    cudaStreamWaitEvent(s2, ev_fork, 0);

    // side stream: hist + scan (independent of gemm)
    hist_kernel<<<(e + 255) / 256, 256, 0, s2>>>(rows, e);
    scan_kernel<<<nb, 256, 0, s2>>>(n);
    cudaEventRecord(ev_join, s2);

    // main stream: gemm concurrent with side stream
    gemm_tc_kernel<<<(n + 127) / 128, 256, SMEM_TOTAL>>>(vecs, b0, att0, att1, attb0, attb1,
                                                         off0, sc0, n);
    cudaStreamWaitEvent(0, ev_join, 0);

    scatter_kernel<<<(e + 255) / 256, 256>>>(adj_vals, rows, cols, e);
    agg_kernel<<<(n + 7) / 8, 256>>>(b1, off1, sc1, out, n);
}

// round 8
// speedup vs baseline: 2.2291x; 1.1056x over previous
#include <cuda_runtime.h>
#include <cuda_bf16.h>
#include <cuda_fp16.h>
#include <cstdint>

#define MAXN 100000
#define MAXE 1600000

// ---------------- scratch (device globals; no allocation allowed) ----------
// B packed: [half(2)][split(2)][kchunk(8)][n(128)][16 bf16] = 131072 bytes
__device__ __align__(16) uint8_t g_Bpk[131072];
__device__ __align__(16) float  g_self[MAXN * 128];
__device__ __align__(16) __half g_vwh[MAXN * 128];     // fp16 vw for edge gather
__device__ __align__(16) float  g_a0[MAXN * 4];
__device__ __align__(16) float  g_a1[MAXN * 4];
__device__ int   g_cnt[MAXN];                          // FULL degree per dest row
__device__ int   g_start[MAXN];
__device__ int   g_cursor[MAXN];
__device__ int   g_ticket;                             // scan tile ticket
__device__ volatile unsigned int g_state[512];         // (status<<30)|sum
__device__ unsigned int g_ecol[MAXE];
__device__ __align__(8) __half g_ewh[MAXE * 4];        // compacted per-record fp16 weights

// ---------------- helpers ---------------------------------------------------
__device__ __forceinline__ uint32_t smem_u32(const void* p) {
    uint32_t a;
    asm("{ .reg .u64 t; cvta.to.shared.u64 t, %1; cvt.u32.u64 %0, t; }" : "=r"(a) : "l"(p));
    return a;
}
__device__ __forceinline__ void ldsm4(uint32_t addr, uint32_t& r0, uint32_t& r1,
                                      uint32_t& r2, uint32_t& r3) {
    asm volatile("ldmatrix.sync.aligned.m8n8.x4.shared.b16 {%0,%1,%2,%3}, [%4];"
                 : "=r"(r0), "=r"(r1), "=r"(r2), "=r"(r3) : "r"(addr));
}
__device__ __forceinline__ void mma16816(float* c, uint32_t a0, uint32_t a1, uint32_t a2,
                                         uint32_t a3, uint32_t b0, uint32_t b1) {
    asm volatile(
        "mma.sync.aligned.m16n8k16.row.col.f32.bf16.bf16.f32 "
        "{%0,%1,%2,%3},{%4,%5,%6,%7},{%8,%9},{%0,%1,%2,%3};"
        : "+f"(c[0]), "+f"(c[1]), "+f"(c[2]), "+f"(c[3])
        : "r"(a0), "r"(a1), "r"(a2), "r"(a3), "r"(b0), "r"(b1));
}

// SMEM: B resident [hf(2)][sp(2)][kc(8)][128][32B] = 131072
//       A [sp(2)][kc(8)][row(128)][32B]            = 65536
//       ex row exchange 128 rows x 2 halves float2 = 2048
#define SMEM_B 0
#define SMEM_A 131072
#define SMEM_EX (131072 + 65536)
#define SMEM_TOTAL (131072 + 65536 + 2048)

// ---------------- kernel 0: pack B (bf16 hi/lo) + zero cnt/scan state ------
__global__ __launch_bounds__(256) void pack_kernel(const float* __restrict__ W0,
                                                   const float* __restrict__ W1, int n) {
    int idx = blockIdx.x * 256 + threadIdx.x;
    if (idx < 32768) {
        int k = idx >> 8;          // 0..127
        int c = idx & 255;         // 0..255 global output col
        float v;
        if (c < 128) {
            v = W0[k * 128 + c];
        } else {
            int j = c - 128;
            int h = j >> 5;
            int k2 = j & 31;
            v = W1[(h * 128 + k) * 32 + k2];
        }
        __nv_bfloat16 hi = __float2bfloat16_rn(v);
        __nv_bfloat16 lo = __float2bfloat16_rn(v - __bfloat162float(hi));
        int hf = c >> 7;
        int nn = c & 127;
        int kc = k >> 4;
        int kk = k & 15;
        int base = ((hf * 2 + 0) * 8 + kc) * 4096 + nn * 32 + kk * 2;
        *reinterpret_cast<__nv_bfloat16*>(g_Bpk + base) = hi;
        *reinterpret_cast<__nv_bfloat16*>(g_Bpk + base + 32768) = lo;   // sp stride = 8*4096
    }
    if (idx < n) g_cnt[idx] = 0;
    if (idx < 512) g_state[idx] = 0;
    if (idx == 0) g_ticket = 0;
}

// ---------------- kernel 1: persistent mma.sync GEMM, fragment epilogues ----
__global__ __launch_bounds__(256, 1) void gemm_tc_kernel(
    const float* __restrict__ vecs, const float* __restrict__ b0,
    const float* __restrict__ att0, const float* __restrict__ att1,
    const float* __restrict__ attb0, const float* __restrict__ attb1,
    const float* __restrict__ off0, const float* __restrict__ sc0, int n, int ntiles) {
    extern __shared__ __align__(1024) char smem[];
    uint32_t sb = smem_u32(smem);
    float2* ex = reinterpret_cast<float2*>(smem + SMEM_EX);
    int tid = threadIdx.x;
    int wid = tid >> 5;
    int lane = tid & 31;

    int mrow0 = (wid & 3) * 32;
    int nbase = (wid >> 2) * 64;
    int rq = lane >> 2;          // row-in-8 selector
    int cq = 2 * (lane & 3);     // col pair selector

    int lt = lane >> 3;
    int l7 = lane & 7;
    int alane = ((lt & 1) * 8 + l7) * 32 + (lt >> 1) * 16;
    int blane = ((lt >> 1) * 8 + l7) * 32 + (lt & 1) * 16;

    // ---- load full B (131072 B) once, resident for kernel lifetime ----
    {
        const uint4* src = reinterpret_cast<const uint4*>(g_Bpk);
        uint4* dst = reinterpret_cast<uint4*>(smem + SMEM_B);
#pragma unroll
        for (int i = 0; i < 32; i++) dst[tid + i * 256] = __ldg(&src[tid + i * 256]);
    }
    __syncthreads();

    float acc[2][8][4];

    auto compute_pass = [&](int hf) {
#pragma unroll
        for (int mt = 0; mt < 2; mt++)
#pragma unroll
            for (int nf = 0; nf < 8; nf++)
#pragma unroll
                for (int q = 0; q < 4; q++) acc[mt][nf][q] = 0.f;
        uint32_t Bbase = sb + SMEM_B + hf * 65536;
        uint32_t Abase = sb + SMEM_A;
#pragma unroll
        for (int kc = 0; kc < 8; kc++) {
            uint32_t ah[2][4], al[2][4];
#pragma unroll
            for (int mt = 0; mt < 2; mt++) {
                uint32_t aaddr = Abase + kc * 4096 + (mrow0 + mt * 16) * 32 + alane;
                ldsm4(aaddr, ah[mt][0], ah[mt][1], ah[mt][2], ah[mt][3]);
                ldsm4(aaddr + 32768, al[mt][0], al[mt][1], al[mt][2], al[mt][3]);
            }
#pragma unroll
            for (int np = 0; np < 4; np++) {
                uint32_t bh[4], bl[4];
                uint32_t baddr = Bbase + kc * 4096 + (nbase + np * 16) * 32 + blane;
                ldsm4(baddr, bh[0], bh[1], bh[2], bh[3]);
                ldsm4(baddr + 32768, bl[0], bl[1], bl[2], bl[3]);
#pragma unroll
                for (int mt = 0; mt < 2; mt++)
#pragma unroll
                    for (int j = 0; j < 2; j++) {
                        float* c = acc[mt][np * 2 + j];
                        mma16816(c, ah[mt][0], ah[mt][1], ah[mt][2], ah[mt][3],
                                 bh[2 * j], bh[2 * j + 1]);
                        mma16816(c, ah[mt][0], ah[mt][1], ah[mt][2], ah[mt][3],
                                 bl[2 * j], bl[2 * j + 1]);
                        mma16816(c, al[mt][0], al[mt][1], al[mt][2], al[mt][3],
                                 bh[2 * j], bh[2 * j + 1]);
                    }
            }
        }
    };

    for (int tile = blockIdx.x; tile < ntiles; tile += gridDim.x) {
        int row0 = tile * 128;

        // ---- load A tile: fp32 -> bf16 hi/lo, [sp][kc][row][32B] ----
#pragma unroll
        for (int it = 0; it < 16; it++) {
            int t = it * 256 + tid;
            int r = t >> 5;
            int q = t & 31;
            float4 v = make_float4(0.f, 0.f, 0.f, 0.f);
            int gr = row0 + r;
            if (gr < n) v = __ldg(reinterpret_cast<const float4*>(vecs + (size_t)gr * 128 + q * 4));
            __nv_bfloat16 h0 = __float2bfloat16_rn(v.x), h1 = __float2bfloat16_rn(v.y);
            __nv_bfloat16 h2 = __float2bfloat16_rn(v.z), h3 = __float2bfloat16_rn(v.w);
            __nv_bfloat16 l0 = __float2bfloat16_rn(v.x - __bfloat162float(h0));
            __nv_bfloat16 l1 = __float2bfloat16_rn(v.y - __bfloat162float(h1));
            __nv_bfloat16 l2 = __float2bfloat16_rn(v.z - __bfloat162float(h2));
            __nv_bfloat16 l3 = __float2bfloat16_rn(v.w - __bfloat162float(h3));
            uint2 hv, lv;
            hv.x = ((uint32_t)__bfloat16_as_ushort(h1) << 16) | __bfloat16_as_ushort(h0);
            hv.y = ((uint32_t)__bfloat16_as_ushort(h3) << 16) | __bfloat16_as_ushort(h2);
            lv.x = ((uint32_t)__bfloat16_as_ushort(l1) << 16) | __bfloat16_as_ushort(l0);
            lv.y = ((uint32_t)__bfloat16_as_ushort(l3) << 16) | __bfloat16_as_ushort(l2);
            int kc = q >> 2;
            int kq = q & 3;
            int off = kc * 4096 + r * 32 + kq * 8;
            *reinterpret_cast<uint2*>(smem + SMEM_A + off) = hv;
            *reinterpret_cast<uint2*>(smem + SMEM_A + 32768 + off) = lv;
        }
        __syncthreads();

        // ===== pass 0: self path (cols 0..127) =====
        compute_pass(0);

        // ---- self epilogue from fragments ----
        {
            float sums[2][2] = {{0.f, 0.f}, {0.f, 0.f}};
            float sqs[2][2] = {{0.f, 0.f}, {0.f, 0.f}};
#pragma unroll
            for (int mt = 0; mt < 2; mt++)
#pragma unroll
                for (int nf = 0; nf < 8; nf++) {
                    int col = nbase + nf * 8 + cq;
                    float ba = __ldg(b0 + col), bb2 = __ldg(b0 + col + 1);
                    float t0 = fmaxf(acc[mt][nf][0] + ba, 0.f);
                    float t1 = fmaxf(acc[mt][nf][1] + bb2, 0.f);
                    float t2 = fmaxf(acc[mt][nf][2] + ba, 0.f);
                    float t3 = fmaxf(acc[mt][nf][3] + bb2, 0.f);
                    sums[mt][0] += t0 + t1; sqs[mt][0] += t0 * t0 + t1 * t1;
                    sums[mt][1] += t2 + t3; sqs[mt][1] += t2 * t2 + t3 * t3;
                }
#pragma unroll
            for (int mk = 1; mk <= 2; mk <<= 1)
#pragma unroll
                for (int mt = 0; mt < 2; mt++)
#pragma unroll
                    for (int hh = 0; hh < 2; hh++) {
                        sums[mt][hh] += __shfl_xor_sync(0xffffffffu, sums[mt][hh], mk);
                        sqs[mt][hh]  += __shfl_xor_sync(0xffffffffu, sqs[mt][hh], mk);
                    }
            int wh = wid >> 2;
            if ((lane & 3) == 0) {
#pragma unroll
                for (int mt = 0; mt < 2; mt++)
#pragma unroll
                    for (int hh = 0; hh < 2; hh++) {
                        int lr = mrow0 + mt * 16 + hh * 8 + rq;
                        ex[lr * 2 + wh] = make_float2(sums[mt][hh], sqs[mt][hh]);
                    }
            }
            __syncthreads();
            float meanv[2][2], rsv[2][2];
#pragma unroll
            for (int mt = 0; mt < 2; mt++)
#pragma unroll
                for (int hh = 0; hh < 2; hh++) {
                    int lr = mrow0 + mt * 16 + hh * 8 + rq;
                    float2 e0 = ex[lr * 2 + 0], e1 = ex[lr * 2 + 1];
                    float sum = e0.x + e1.x, sq = e0.y + e1.y;
                    float mean = sum * (1.f / 128.f);
                    float var = fmaxf(sq * (1.f / 128.f) - mean * mean, 0.f);
                    meanv[mt][hh] = mean;
                    rsv[mt][hh] = rsqrtf(var + 1e-9f);
                }
#pragma unroll
            for (int mt = 0; mt < 2; mt++) {
                int r0g = row0 + mrow0 + mt * 16 + rq;
#pragma unroll
                for (int nf = 0; nf < 8; nf++) {
                    int col = nbase + nf * 8 + cq;
                    float ba = __ldg(b0 + col), bb2 = __ldg(b0 + col + 1);
                    float sa = __ldg(sc0 + col), sb2 = __ldg(sc0 + col + 1);
                    float oa = __ldg(off0 + col), ob = __ldg(off0 + col + 1);
                    if (r0g < n) {
                        float t0 = fmaxf(acc[mt][nf][0] + ba, 0.f);
                        float t1 = fmaxf(acc[mt][nf][1] + bb2, 0.f);
                        *reinterpret_cast<float2*>(&g_self[(size_t)r0g * 128 + col]) =
                            make_float2(sa * (t0 - meanv[mt][0]) * rsv[mt][0] + oa,
                                        sb2 * (t1 - meanv[mt][0]) * rsv[mt][0] + ob);
                    }
                    if (r0g + 8 < n) {
                        float t2 = fmaxf(acc[mt][nf][2] + ba, 0.f);
                        float t3 = fmaxf(acc[mt][nf][3] + bb2, 0.f);
                        *reinterpret_cast<float2*>(&g_self[(size_t)(r0g + 8) * 128 + col]) =
                            make_float2(sa * (t2 - meanv[mt][1]) * rsv[mt][1] + oa,
                                        sb2 * (t3 - meanv[mt][1]) * rsv[mt][1] + ob);
                    }
                }
            }
        }

        // ===== pass 1: vw path (cols 128..255) =====
        compute_pass(1);

        // ---- vw epilogue: fp16 stores + attention dots from fragments ----
        {
            int h0 = nbase >> 5;
            float d0p[2][2][2], d1p[2][2][2];
#pragma unroll
            for (int mt = 0; mt < 2; mt++)
#pragma unroll
                for (int hh = 0; hh < 2; hh++)
#pragma unroll
                    for (int hs = 0; hs < 2; hs++) { d0p[mt][hh][hs] = 0.f; d1p[mt][hh][hs] = 0.f; }
#pragma unroll
            for (int mt = 0; mt < 2; mt++) {
                int r0g = row0 + mrow0 + mt * 16 + rq;
#pragma unroll
                for (int nf = 0; nf < 8; nf++) {
                    int col = nbase + nf * 8 + cq;
                    float a00 = __ldg(att0 + col), a01 = __ldg(att0 + col + 1);
                    float a10 = __ldg(att1 + col), a11 = __ldg(att1 + col + 1);
                    float v0 = acc[mt][nf][0], v1 = acc[mt][nf][1];
                    float v2 = acc[mt][nf][2], v3 = acc[mt][nf][3];
                    if (r0g < n) {
                        __half2 p = __floats2half2_rn(v0, v1);
                        *reinterpret_cast<__half2*>(&g_vwh[(size_t)r0g * 128 + col]) = p;
                    }
                    if (r0g + 8 < n) {
                        __half2 p = __floats2half2_rn(v2, v3);
                        *reinterpret_cast<__half2*>(&g_vwh[(size_t)(r0g + 8) * 128 + col]) = p;
                    }
                    int hs = nf >> 2;
                    d0p[mt][0][hs] += v0 * a00 + v1 * a01;
                    d0p[mt][1][hs] += v2 * a00 + v3 * a01;
                    d1p[mt][0][hs] += v0 * a10 + v1 * a11;
                    d1p[mt][1][hs] += v2 * a10 + v3 * a11;
                }
            }
#pragma unroll
            for (int mk = 1; mk <= 2; mk <<= 1)
#pragma unroll
                for (int mt = 0; mt < 2; mt++)
#pragma unroll
                    for (int hh = 0; hh < 2; hh++)
#pragma unroll
                        for (int hs = 0; hs < 2; hs++) {
                            d0p[mt][hh][hs] += __shfl_xor_sync(0xffffffffu, d0p[mt][hh][hs], mk);
                            d1p[mt][hh][hs] += __shfl_xor_sync(0xffffffffu, d1p[mt][hh][hs], mk);
                        }
            if ((lane & 3) == 0) {
#pragma unroll
                for (int mt = 0; mt < 2; mt++)
#pragma unroll
                    for (int hh = 0; hh < 2; hh++) {
                        int rg = row0 + mrow0 + mt * 16 + hh * 8 + rq;
                        if (rg < n) {
#pragma unroll
                            for (int hs = 0; hs < 2; hs++) {
                                g_a0[(size_t)rg * 4 + h0 + hs] =
                                    d0p[mt][hh][hs] + __ldg(attb0 + h0 + hs);
                                g_a1[(size_t)rg * 4 + h0 + hs] =
                                    d1p[mt][hh][hs] + __ldg(attb1 + h0 + hs);
                            }
                        }
                    }
            }
        }
        __syncthreads();   // protect A + ex before next tile overwrites
    }
}

// ---------------- kernel 2: full-degree histogram ----------------------------
__global__ __launch_bounds__(256) void hist_kernel(const int* __restrict__ rows, int e) {
    int i = blockIdx.x * 256 + threadIdx.x;
    if (i >= e) return;
    atomicAdd(&g_cnt[__ldg(rows + i)], 1);
}

// ---------------- kernel 3: single-pass decoupled-lookback scan -------------
__global__ __launch_bounds__(256) void scan_kernel(int n) {
    __shared__ int s_bid;
    __shared__ int s_wsum[8];
    __shared__ int s_prefix;
    int tid = threadIdx.x;
    int wid = tid >> 5;
    int lane = tid & 31;

    if (tid == 0) s_bid = atomicAdd(&g_ticket, 1);
    __syncthreads();
    int bid = s_bid;

    int i = bid * 256 + tid;
    int v = (i < n) ? g_cnt[i] : 0;

    int incl = v;
#pragma unroll
    for (int m = 1; m < 32; m <<= 1) {
        int x = __shfl_up_sync(0xffffffffu, incl, m);
        if (lane >= m) incl += x;
    }
    if (lane == 31) s_wsum[wid] = incl;
    __syncthreads();
    if (wid == 0 && lane < 8) {
        int w = s_wsum[lane];
#pragma unroll
        for (int m = 1; m < 8; m <<= 1) {
            int x = __shfl_up_sync(0xffu, w, m);
            if (lane >= m) w += x;
        }
        s_wsum[lane] = w;
    }
    __syncthreads();
    int blocksum = s_wsum[7];
    if (wid > 0) incl += s_wsum[wid - 1];

    if (tid == 0) {
        unsigned int tag = (bid == 0) ? ((2u << 30) | (unsigned int)blocksum)
                                      : ((1u << 30) | (unsigned int)blocksum);
        g_state[bid] = tag;
        __threadfence();
    }

    if (wid == 0) {
        int prefix = 0;
        if (bid > 0) {
            int look = bid - 1;
            while (true) {
                int idx2 = look - lane;
                unsigned int st;
                if (idx2 < 0) {
                    st = (2u << 30);
                } else {
                    do { st = g_state[idx2]; } while ((st >> 30) == 0u);
                }
                unsigned int status = st >> 30;
                int val = (int)(st & 0x3FFFFFFFu);
                unsigned int ball = __ballot_sync(0xffffffffu, status >= 2u);
                if (ball) {
                    int first = __ffs(ball) - 1;
                    int contrib = (lane <= first) ? val : 0;
#pragma unroll
                    for (int m = 16; m > 0; m >>= 1)
                        contrib += __shfl_xor_sync(0xffffffffu, contrib, m);
                    prefix += contrib;
                    break;
                } else {
                    int contrib = val;
#pragma unroll
                    for (int m = 16; m > 0; m >>= 1)
                        contrib += __shfl_xor_sync(0xffffffffu, contrib, m);
                    prefix += contrib;
                    look -= 32;
                }
            }
            if (lane == 0) {
                g_state[bid] = (2u << 30) | (unsigned int)(prefix + blocksum);
                __threadfence();
            }
        }
        if (lane == 0) s_prefix = prefix;
    }
    __syncthreads();

    if (i < n) {
        int start = s_prefix + incl - v;
        g_start[i] = start;
        g_cursor[i] = start;
    }
}

// ---------------- kernel 4: compute weights, filter, compact ----------------
__global__ __launch_bounds__(256) void scatter_kernel(const float* __restrict__ vals,
                                                      const int* __restrict__ rows,
                                                      const int* __restrict__ cols, int e) {
    int i = blockIdx.x * 256 + threadIdx.x;
    if (i >= e) return;
    int r = __ldg(rows + i);
    int c = __ldg(cols + i);
    float val = __ldg(vals + i);
    float4 ar = __ldg(reinterpret_cast<const float4*>(&g_a0[(size_t)r * 4]));
    float4 ac = __ldg(reinterpret_cast<const float4*>(&g_a1[(size_t)c * 4]));
    float w0 = val * fmaxf(ar.x + ac.x, 0.f);
    float w1 = val * fmaxf(ar.y + ac.y, 0.f);
    float w2 = val * fmaxf(ar.z + ac.z, 0.f);
    float w3 = val * fmaxf(ar.w + ac.w, 0.f);
    if (w0 + w1 + w2 + w3 > 0.f) {
        int pos = atomicAdd(&g_cursor[r], 1);
        g_ecol[pos] = (unsigned int)c;
        __half2 p0 = __floats2half2_rn(w0, w1);
        __half2 p1 = __floats2half2_rn(w2, w3);
        uint2 pk;
        pk.x = *reinterpret_cast<uint32_t*>(&p0);
        pk.y = *reinterpret_cast<uint32_t*>(&p1);
        *reinterpret_cast<uint2*>(&g_ewh[(size_t)pos * 4]) = pk;
    }
}

// ---------------- kernel 5: per-row aggregation + fused epilogue ------------
__global__ __launch_bounds__(256) void agg_kernel(const float* __restrict__ b1,
                                                  const float* __restrict__ off1,
                                                  const float* __restrict__ sc1,
                                                  float* __restrict__ out, int n) {
    int r = (blockIdx.x << 3) + (threadIdx.x >> 5);
    if (r >= n) return;
    int lane = threadIdx.x & 31;
    int j = lane << 2;
    int h = lane >> 3;

    int start = g_start[r];
    int deg = g_cursor[r] - start;

    float4 acc = make_float4(0.f, 0.f, 0.f, 0.f);

    auto gather = [&](unsigned int c, float w) {
        uint2 pk = __ldg(reinterpret_cast<const uint2*>(&g_vwh[(size_t)c * 128 + j]));
        float2 v0 = __half22float2(*reinterpret_cast<__half2*>(&pk.x));
        float2 v1 = __half22float2(*reinterpret_cast<__half2*>(&pk.y));
        acc.x += w * v0.x;
        acc.y += w * v0.y;
        acc.z += w * v1.x;
        acc.w += w * v1.y;
    };

    int i = 0;
    for (; i + 4 <= deg; i += 4) {
        unsigned int c0 = __ldg(&g_ecol[start + i + 0]);
        unsigned int c1 = __ldg(&g_ecol[start + i + 1]);
        unsigned int c2 = __ldg(&g_ecol[start + i + 2]);
        unsigned int c3 = __ldg(&g_ecol[start + i + 3]);
        float w0 = __half2float(__ldg(&g_ewh[(size_t)(start + i + 0) * 4 + h]));
        float w1 = __half2float(__ldg(&g_ewh[(size_t)(start + i + 1) * 4 + h]));
        float w2 = __half2float(__ldg(&g_ewh[(size_t)(start + i + 2) * 4 + h]));
        float w3 = __half2float(__ldg(&g_ewh[(size_t)(start + i + 3) * 4 + h]));
        if (w0 > 0.f) gather(c0, w0);
        if (w1 > 0.f) gather(c1, w1);
        if (w2 > 0.f) gather(c2, w2);
        if (w3 > 0.f) gather(c3, w3);
    }
    for (; i < deg; i++) {
        unsigned int c = __ldg(&g_ecol[start + i]);
        float w = __half2float(__ldg(&g_ewh[(size_t)(start + i) * 4 + h]));
        if (w > 0.f) gather(c, w);
    }

    float t0 = fmaxf(acc.x, 0.f) + b1[j + 0];
    float t1 = fmaxf(acc.y, 0.f) + b1[j + 1];
    float t2 = fmaxf(acc.z, 0.f) + b1[j + 2];
    float t3 = fmaxf(acc.w, 0.f) + b1[j + 3];
    float sum = t0 + t1 + t2 + t3;
    float sq = t0 * t0 + t1 * t1 + t2 * t2 + t3 * t3;
#pragma unroll
    for (int m = 16; m > 0; m >>= 1) {
        sum += __shfl_xor_sync(0xffffffffu, sum, m);
        sq  += __shfl_xor_sync(0xffffffffu, sq, m);
    }
    float mean = sum * (1.f / 128.f);
    float var = fmaxf(sq * (1.f / 128.f) - mean * mean, 0.f);
    float rs = rsqrtf(var + 1e-9f);
    float4 s = *reinterpret_cast<const float4*>(&g_self[(size_t)r * 128 + j]);
    float4 o;
    o.x = sc1[j + 0] * (t0 - mean) * rs + off1[j + 0] + s.x;
    o.y = sc1[j + 1] * (t1 - mean) * rs + off1[j + 1] + s.y;
    o.z = sc1[j + 2] * (t2 - mean) * rs + off1[j + 2] + s.z;
    o.w = sc1[j + 3] * (t3 - mean) * rs + off1[j + 3] + s.w;
    *reinterpret_cast<float4*>(&out[(size_t)r * 128 + j]) = o;
}

// ---------------- launch ----------------------------------------------------
extern "C" void kernel_launch(void* const* d_in, const int* in_sizes, int n_in,
                              void* d_out, int out_size) {
    const float* vecs     = (const float*)d_in[0];
    const float* adj_vals = (const float*)d_in[1];
    const float* W0       = (const float*)d_in[2];
    const float* b0       = (const float*)d_in[3];
    const float* W1       = (const float*)d_in[4];
    const float* b1       = (const float*)d_in[5];
    const float* att0     = (const float*)d_in[6];
    const float* att1     = (const float*)d_in[7];
    const float* attb0    = (const float*)d_in[8];
    const float* attb1    = (const float*)d_in[9];
    const float* off0     = (const float*)d_in[10];
    const float* sc0      = (const float*)d_in[11];
    const float* off1     = (const float*)d_in[12];
    const float* sc1      = (const float*)d_in[13];
    const int*   rows     = (const int*)d_in[14];
    const int*   cols     = (const int*)d_in[15];

    int n = in_sizes[0] / 128;
    int e = in_sizes[1];
    float* out = (float*)d_out;

    int nb = (n + 255) / 256;
    int nbp = nb < 128 ? 128 : nb;
    int ntiles = (n + 127) / 128;
    int grid = ntiles < 152 ? ntiles : 152;

    static cudaStream_t s2 = nullptr;
    static cudaEvent_t ev_fork = nullptr, ev_join = nullptr;
    static int smem_set = 0;
    if (!smem_set) {
        cudaFuncSetAttribute(gemm_tc_kernel, cudaFuncAttributeMaxDynamicSharedMemorySize,
                             SMEM_TOTAL);
        cudaStreamCreateWithFlags(&s2, cudaStreamNonBlocking);
        cudaEventCreateWithFlags(&ev_fork, cudaEventDisableTiming);
        cudaEventCreateWithFlags(&ev_join, cudaEventDisableTiming);
        smem_set = 1;
    }

    pack_kernel<<<nbp, 256>>>(W0, W1, n);
    cudaEventRecord(ev_fork, 0);
    cudaStreamWaitEvent(s2, ev_fork, 0);

    hist_kernel<<<(e + 255) / 256, 256, 0, s2>>>(rows, e);
    scan_kernel<<<nb, 256, 0, s2>>>(n);
    cudaEventRecord(ev_join, s2);

    gemm_tc_kernel<<<grid, 256, SMEM_TOTAL>>>(vecs, b0, att0, att1, attb0, attb1,
                                              off0, sc0, n, ntiles);
    cudaStreamWaitEvent(0, ev_join, 0);

    scatter_kernel<<<(e + 255) / 256, 256>>>(adj_vals, rows, cols, e);
    agg_kernel<<<(n + 7) / 8, 256>>>(b1, off1, sc1, out, n);
}